// round 11
// baseline (speedup 1.0000x reference)
#include <cuda_runtime.h>
#include <cstdint>

// ---------------------------------------------------------------------------
// Problem constants
// ---------------------------------------------------------------------------
#define BATCH   8192
#define CDIM    1024

// ---------------------------------------------------------------------------
// Device scratch (layouts identical to round-10 passing kernel)
// ---------------------------------------------------------------------------
__device__ float g_Xq[(size_t)BATCH * 1024u];
__device__ float g_Xk[(size_t)BATCH * 1024u];
__device__ float g_Xv[(size_t)BATCH * 1024u];
__device__ float g_Wq[917504u];          // 14 * 512*128
__device__ float g_Wk[917504u];
__device__ float g_Wv[917504u];
__device__ float g_Wf[917504u];          // 14 * 128*512
__device__ float g_Yq[(size_t)BATCH * 4096u];
__device__ float g_Yk[(size_t)BATCH * 4096u];
__device__ float g_Yv[(size_t)BATCH * 4096u];
__device__ float g_Zh[(size_t)BATCH * 4096u];
__device__ float g_Yf[(size_t)BATCH * 1024u];
__device__ float g_attn_dummy[(size_t)BATCH * 512u];

// ---------------------------------------------------------------------------
// GEMM job tables (mode 0 = projection, 1 = fc)
// ---------------------------------------------------------------------------
__constant__ int c_aoff[2][8] = {{0, 256, 256, 512, 512, 768, 768, 128},
                                 {0, 1024, 1024, 2048, 2048, 3072, 3072, 512}};
__constant__ int c_kk[2][8]   = {{128, 256, 256, 256, 256, 256, 256, 128},
                                 {512, 1024, 1024, 1024, 1024, 1024, 1024, 512}};
__constant__ int c_woff[8]    = {0, 65536, 196608, 327680, 458752, 589824, 720896, 851968};
__constant__ int c_coff[2][8] = {{0, 512, 1024, 1536, 2048, 2560, 3072, 3584},
                                 {0, 128, 256, 384, 512, 640, 768, 896}};

// ---------------------------------------------------------------------------
// FFT8 helpers
// ---------------------------------------------------------------------------
#define C1F 0.70710678118654752f

__device__ __forceinline__ void fft8(const float* x, float* f) {
    float t0 = x[0] + x[4], t4 = x[0] - x[4];
    float t1 = x[1] + x[5], t5 = x[1] - x[5];
    float t2 = x[2] + x[6], t6 = x[2] - x[6];
    float t3 = x[3] + x[7], t7 = x[3] - x[7];
    f[0] = t0 + t1 + t2 + t3;
    f[7] = t0 - t1 + t2 - t3;
    f[3] = t0 - t2;
    f[4] = t3 - t1;
    float a = C1F * (t5 - t7), b = C1F * (t5 + t7);
    f[1] = t4 + a;
    f[2] = -t6 - b;
    f[5] = t4 - a;
    f[6] = t6 - b;
}

__device__ __forceinline__ void ifft8(const float* f, float* y) {
    float u0 = 0.5f * (f[0] + f[7]);
    float u1 = 0.5f * (f[0] - f[7]);
    float t0 = 0.5f * (u0 + f[3]);
    float t2 = 0.5f * (u0 - f[3]);
    float t3 = 0.5f * (u1 + f[4]);
    float t1 = 0.5f * (u1 - f[4]);
    float t4 = 0.5f * (f[1] + f[5]);
    float d57 = (f[1] - f[5]) * (0.5f / C1F);
    float t6 = 0.5f * (f[6] - f[2]);
    float s57 = -(f[2] + f[6]) * (0.5f / C1F);
    float t5 = 0.5f * (s57 + d57);
    float t7 = 0.5f * (s57 - d57);
    y[0] = 0.5f * (t0 + t4);  y[4] = 0.5f * (t0 - t4);
    y[1] = 0.5f * (t1 + t5);  y[5] = 0.5f * (t1 - t5);
    y[2] = 0.5f * (t2 + t6);  y[6] = 0.5f * (t2 - t6);
    y[3] = 0.5f * (t3 + t7);  y[7] = 0.5f * (t3 - t7);
}

// ---------------------------------------------------------------------------
// Fused activation forward FFT for q,k,v (grid.y selects tensor)
// ---------------------------------------------------------------------------
__global__ __launch_bounds__(256)
void act_fft3_kernel(const float* __restrict__ x0, const float* __restrict__ x1,
                     const float* __restrict__ x2,
                     float* __restrict__ h0, float* __restrict__ h1,
                     float* __restrict__ h2) {
    __shared__ float s[2 * 1152];
    int blk = blockIdx.x, tid = threadIdx.x;
    const float* x = (blockIdx.y == 0) ? x0 : (blockIdx.y == 1) ? x1 : x2;
    float* xh      = (blockIdx.y == 0) ? h0 : (blockIdx.y == 1) ? h1 : h2;
    size_t base = (size_t)blk * 2048;
#pragma unroll
    for (int i = 0; i < 2; i++) {
        int e = tid + i * 256;
        int row = e >> 8, c4 = e & 255;
        float4 v = reinterpret_cast<const float4*>(x + base + row * 1024)[c4];
        int k = c4 * 4;
        float* d = s + row * 1152 + k + (k >> 3);
        d[0] = v.x; d[1] = v.y; d[2] = v.z; d[3] = v.w;
    }
    __syncthreads();
    int row = tid >> 7, o = tid & 127;
    float xx[8], f[8];
    const float* sp = s + row * 1152 + o * 9;
#pragma unroll
    for (int j = 0; j < 8; j++) xx[j] = sp[j];
    fft8(xx, f);
    size_t ob = (size_t)(blk * 2 + row) * 1024;
    xh[ob + o]       = f[0];
    xh[ob + 128 + o] = f[7];
    xh[ob + 256 + o] = f[1];
    xh[ob + 384 + o] = f[2];
    xh[ob + 512 + o] = f[3];
    xh[ob + 640 + o] = f[4];
    xh[ob + 768 + o] = f[5];
    xh[ob + 896 + o] = f[6];
}

// ---------------------------------------------------------------------------
// Fused weight FFT + job stacking for all 4 weights (grid.y selects weight)
// ---------------------------------------------------------------------------
__global__ void wfft4_kernel(const float* __restrict__ w0, const float* __restrict__ w1,
                             const float* __restrict__ w2, const float* __restrict__ w3,
                             float* __restrict__ s0, float* __restrict__ s1,
                             float* __restrict__ s2, float* __restrict__ s3) {
    int which = blockIdx.y;
    const float* w = (which == 0) ? w0 : (which == 1) ? w1 : (which == 2) ? w2 : w3;
    float* ws      = (which == 0) ? s0 : (which == 1) ? s1 : (which == 2) ? s2 : s3;
    int I = (which == 3) ? 512 : 128;
    int e = blockIdx.x * blockDim.x + threadIdx.x;   // e < 65536 = O*I
    int o = e / I, i = e - o * I;
    float xx[8], f[8];
    const float* wp = w + (size_t)e * 8;
#pragma unroll
    for (int j = 0; j < 8; j++) xx[j] = wp[j];
    fft8(xx, f);
    const size_t OI = 65536u;
    ws[e] = f[0];
    ws[13 * OI + e] = f[7];
#pragma unroll
    for (int m = 1; m <= 3; m++) {
        float re = f[2 * m - 1], im = f[2 * m];
        size_t j1 = OI * (size_t)(4 * m - 3);
        size_t j2 = OI * (size_t)(4 * m - 1);
        size_t rb = (size_t)o * 2 * I + i;
        ws[j1 + rb]     = re;
        ws[j1 + rb + I] = -im;
        ws[j2 + rb]     = im;
        ws[j2 + rb + I] = re;
    }
}

// ---------------------------------------------------------------------------
// GEMM: C = A * B^T per frequency job; split-2 bf16, 3 passes.
// Occupancy-2 variant: pass-sequential fragment loads to cap registers.
// ---------------------------------------------------------------------------
#define TM 128
#define TN 128
#define TK 32
#define PADK 40
#define TILE_H (128 * PADK)
#define STAGE_H (4 * TILE_H)
#define GEMM_SMEM_BYTES (2 * STAGE_H * 2)   // 81,920 B

__device__ __forceinline__ void mma16816(float* c, const uint32_t* a, const uint32_t* b) {
    asm volatile(
        "mma.sync.aligned.m16n8k16.row.col.f32.bf16.bf16.f32 "
        "{%0,%1,%2,%3}, {%4,%5,%6,%7}, {%8,%9}, {%0,%1,%2,%3};"
        : "+f"(c[0]), "+f"(c[1]), "+f"(c[2]), "+f"(c[3])
        : "r"(a[0]), "r"(a[1]), "r"(a[2]), "r"(a[3]), "r"(b[0]), "r"(b[1]));
}

__device__ __forceinline__ void split_sts(float4 v, uint16_t* ph, uint16_t* pl) {
    uint32_t ux = __float_as_uint(v.x), uy = __float_as_uint(v.y);
    uint32_t uz = __float_as_uint(v.z), uw = __float_as_uint(v.w);
    uint32_t h0 = __byte_perm(ux, uy, 0x7632);
    uint32_t h1 = __byte_perm(uz, uw, 0x7632);
    float lx = v.x - __uint_as_float(ux & 0xffff0000u);
    float ly = v.y - __uint_as_float(uy & 0xffff0000u);
    float lz = v.z - __uint_as_float(uz & 0xffff0000u);
    float lw = v.w - __uint_as_float(uw & 0xffff0000u);
    uint32_t l0, l1;
    asm("cvt.rn.bf16x2.f32 %0, %1, %2;" : "=r"(l0) : "f"(ly), "f"(lx));
    asm("cvt.rn.bf16x2.f32 %0, %1, %2;" : "=r"(l1) : "f"(lw), "f"(lz));
    uint2 hv; hv.x = h0; hv.y = h1;
    uint2 lv; lv.x = l0; lv.y = l1;
    *reinterpret_cast<uint2*>(ph) = hv;
    *reinterpret_cast<uint2*>(pl) = lv;
}

__global__ __launch_bounds__(256, 2)
void gemm_freq(const float* __restrict__ Xh, const float* __restrict__ Ws,
               float* __restrict__ Ch, int lda, int ldc, int mode)
{
    extern __shared__ uint16_t sm16[];

    const int z    = blockIdx.z;
    const int K    = c_kk[mode][z];
    const int aoff = c_aoff[mode][z];
    const int coff = c_coff[mode][z];

    const int tid  = threadIdx.x;
    const int wid  = tid >> 5, lane = tid & 31;
    const int wm   = wid >> 2, wn = wid & 3;
    const int q    = lane >> 2;
    const int t4   = (lane & 3) * 2;

    const size_t m0 = (size_t)blockIdx.y * TM;
    const float* Ab = Xh + m0 * (size_t)lda + aoff;
    const float* Bb = Ws + (size_t)c_woff[z] + (size_t)blockIdx.x * 128 * (size_t)K;

    float acc[4][4][4];
#pragma unroll
    for (int i = 0; i < 4; i++)
#pragma unroll
        for (int j = 0; j < 4; j++)
#pragma unroll
            for (int r = 0; r < 4; r++) acc[i][j][r] = 0.f;

    float4 ra[4], rb[4];
#pragma unroll
    for (int i = 0; i < 4; i++) {
        int e = tid + i * 256, row = e >> 3, k4 = (e & 7) * 4;
        ra[i] = *reinterpret_cast<const float4*>(Ab + (size_t)row * lda + k4);
        rb[i] = *reinterpret_cast<const float4*>(Bb + (size_t)row * K + k4);
    }

    const int NC = K / TK;
    for (int c = 0; c < NC; c++) {
        const int s = c & 1;
        uint16_t* Ah = sm16 + s * STAGE_H;
        uint16_t* Al = Ah + TILE_H;
        uint16_t* Bh = Ah + 2 * TILE_H;
        uint16_t* Bl = Ah + 3 * TILE_H;

#pragma unroll
        for (int i = 0; i < 4; i++) {
            int e = tid + i * 256, row = e >> 3, k4 = (e & 7) * 4;
            int off = row * PADK + k4;
            split_sts(ra[i], Ah + off, Al + off);
            split_sts(rb[i], Bh + off, Bl + off);
        }
        __syncthreads();

        if (c + 1 < NC) {
            int k0 = (c + 1) * TK;
#pragma unroll
            for (int i = 0; i < 4; i++) {
                int e = tid + i * 256, row = e >> 3, k4 = (e & 7) * 4;
                ra[i] = *reinterpret_cast<const float4*>(Ab + (size_t)row * lda + k0 + k4);
                rb[i] = *reinterpret_cast<const float4*>(Bb + (size_t)row * K + k0 + k4);
            }
        }

#pragma unroll
        for (int ks = 0; ks < 2; ks++) {
            const int kb = ks * 16;
            uint32_t ah[4][4], bx[4][2], t[4][4];
            // ---- pass 1: ah * bh
#pragma unroll
            for (int i = 0; i < 4; i++) {
                int r = wm * 64 + i * 16 + q;
                int o00 = r * PADK + kb + t4;
                int o10 = (r + 8) * PADK + kb + t4;
                ah[i][0] = *reinterpret_cast<const uint32_t*>(Ah + o00);
                ah[i][1] = *reinterpret_cast<const uint32_t*>(Ah + o10);
                ah[i][2] = *reinterpret_cast<const uint32_t*>(Ah + o00 + 8);
                ah[i][3] = *reinterpret_cast<const uint32_t*>(Ah + o10 + 8);
            }
#pragma unroll
            for (int j = 0; j < 4; j++) {
                int r = wn * 32 + j * 8 + q;
                int o0 = r * PADK + kb + t4;
                bx[j][0] = *reinterpret_cast<const uint32_t*>(Bh + o0);
                bx[j][1] = *reinterpret_cast<const uint32_t*>(Bh + o0 + 8);
            }
#pragma unroll
            for (int i = 0; i < 4; i++)
#pragma unroll
                for (int j = 0; j < 4; j++) mma16816(acc[i][j], ah[i], bx[j]);
            // ---- pass 2: al * bh  (al loaded into t)
#pragma unroll
            for (int i = 0; i < 4; i++) {
                int r = wm * 64 + i * 16 + q;
                int o00 = r * PADK + kb + t4;
                int o10 = (r + 8) * PADK + kb + t4;
                t[i][0] = *reinterpret_cast<const uint32_t*>(Al + o00);
                t[i][1] = *reinterpret_cast<const uint32_t*>(Al + o10);
                t[i][2] = *reinterpret_cast<const uint32_t*>(Al + o00 + 8);
                t[i][3] = *reinterpret_cast<const uint32_t*>(Al + o10 + 8);
            }
#pragma unroll
            for (int i = 0; i < 4; i++)
#pragma unroll
                for (int j = 0; j < 4; j++) mma16816(acc[i][j], t[i], bx[j]);
            // ---- pass 3: ah * bl  (bl overwrites bx)
#pragma unroll
            for (int j = 0; j < 4; j++) {
                int r = wn * 32 + j * 8 + q;
                int o0 = r * PADK + kb + t4;
                bx[j][0] = *reinterpret_cast<const uint32_t*>(Bl + o0);
                bx[j][1] = *reinterpret_cast<const uint32_t*>(Bl + o0 + 8);
            }
#pragma unroll
            for (int i = 0; i < 4; i++)
#pragma unroll
                for (int j = 0; j < 4; j++) mma16816(acc[i][j], ah[i], bx[j]);
        }
        __syncthreads();
    }

    const int nbase = coff + blockIdx.x * 128;
#pragma unroll
    for (int i = 0; i < 4; i++) {
        size_t r = m0 + wm * 64 + i * 16 + q;
#pragma unroll
        for (int j = 0; j < 4; j++) {
            int cl = nbase + wn * 32 + j * 8 + t4;
            float2 v0, v1;
            v0.x = acc[i][j][0]; v0.y = acc[i][j][1];
            v1.x = acc[i][j][2]; v1.y = acc[i][j][3];
            *reinterpret_cast<float2*>(Ch + r * ldc + cl)       = v0;
            *reinterpret_cast<float2*>(Ch + (r + 8) * ldc + cl) = v1;
        }
    }
}

// ---------------------------------------------------------------------------
// Attention (identical to round-10 passing kernel)
// ---------------------------------------------------------------------------
#define ROWSTR 516
#define ZBUF_OFF (24 * ROWSTR)
#define ATTN_SMEM ((24 * ROWSTR + 4608) * 4)

__global__ __launch_bounds__(256)
void attn_freq_kernel(const float* __restrict__ Yq, const float* __restrict__ Yk,
                      const float* __restrict__ Yv,
                      const float* __restrict__ bq, const float* __restrict__ bk,
                      const float* __restrict__ bv,
                      float* __restrict__ Zhat, float* __restrict__ attn_out)
{
    extern __shared__ float sm[];
    float* sQ = sm;
    float* sK = sm + 8 * ROWSTR;
    float* sV = sm + 16 * ROWSTR;
    float* zb = sm + ZBUF_OFF;

    int b   = blockIdx.x;
    int tid = threadIdx.x;

    const float* srcs[3] = {Yq + (size_t)b * 4096, Yk + (size_t)b * 4096,
                            Yv + (size_t)b * 4096};
    const float* bss[3]  = {bq, bk, bv};
    float* dsts[3] = {sQ, sK, sV};
#pragma unroll
    for (int t3 = 0; t3 < 3; t3++) {
        const float* S = srcs[t3];
        const float* Bp = bss[t3];
        float* D = dsts[t3];
        for (int o = tid; o < 512; o += 256) {
            float f[8], y[8];
#pragma unroll
            for (int p = 0; p < 8; p++) f[p] = S[p * 512 + o];
            ifft8(f, y);
            float bias = Bp[o];
            float* dp = D + (o >> 6) * ROWSTR + (o & 63) * 8;
#pragma unroll
            for (int g = 0; g < 8; g++) dp[g] = y[g] + bias;
        }
    }
    __syncthreads();

    int w    = tid >> 5;
    int lane = tid & 31;
    int base = w * 64;
    int g1a  = lane >> 3;
    int g2   = lane & 7;
    int g1b  = g1a + 4;

    const float* qa = sQ + g1a * ROWSTR + base;
    const float* qb = sQ + g1b * ROWSTR + base;
    const float* kr = sK + g2  * ROWSTR + base;
    float s0 = 0.f, s1 = 0.f;
#pragma unroll 8
    for (int d = 0; d < 64; d++) {
        float kv = kr[d];
        s0 = fmaf(qa[d], kv, s0);
        s1 = fmaf(qb[d], kv, s1);
    }
    s0 *= 0.125f; s1 *= 0.125f;

    float m0 = s0, m1 = s1;
#pragma unroll
    for (int off = 4; off; off >>= 1) {
        m0 = fmaxf(m0, __shfl_xor_sync(0xffffffffu, m0, off));
        m1 = fmaxf(m1, __shfl_xor_sync(0xffffffffu, m1, off));
    }
    float e0 = __expf(s0 - m0), e1 = __expf(s1 - m1);
    float z0 = e0, z1 = e1;
#pragma unroll
    for (int off = 4; off; off >>= 1) {
        z0 += __shfl_xor_sync(0xffffffffu, z0, off);
        z1 += __shfl_xor_sync(0xffffffffu, z1, off);
    }
    float a0 = e0 / z0, a1 = e1 / z1;

    attn_out[(size_t)b * 512 + base + lane]      = a0;
    attn_out[(size_t)b * 512 + base + 32 + lane] = a1;

    __syncwarp();
    sQ[g1a * ROWSTR + base + g2] = a0;
    sQ[g1b * ROWSTR + base + g2] = a1;
    __syncwarp();

#pragma unroll
    for (int g1 = 0; g1 < 8; g1++) {
        const float* ar = sQ + g1 * ROWSTR + base;
        float acc0 = 0.f, acc1 = 0.f;
#pragma unroll
        for (int j = 0; j < 8; j++) {
            float a = ar[j];
            acc0 = fmaf(a, sV[j * ROWSTR + base + lane],      acc0);
            acc1 = fmaf(a, sV[j * ROWSTR + base + 32 + lane], acc1);
        }
        int n0 = g1 * 512 + base + lane;
        int n1 = n0 + 32;
        zb[n0 + (n0 >> 3)] = acc0;
        zb[n1 + (n1 >> 3)] = acc1;
    }
    __syncthreads();

    size_t zr = (size_t)b * 4096;
    for (int o = tid; o < 512; o += 256) {
        float xx[8], f[8];
        const float* zp = zb + o * 9;
#pragma unroll
        for (int j = 0; j < 8; j++) xx[j] = zp[j];
        fft8(xx, f);
        Zhat[zr + o]         = f[0];
        Zhat[zr + 512 + o]   = f[7];
        Zhat[zr + 1024 + o]  = f[1];
        Zhat[zr + 1536 + o]  = f[2];
        Zhat[zr + 2048 + o]  = f[3];
        Zhat[zr + 2560 + o]  = f[4];
        Zhat[zr + 3072 + o]  = f[5];
        Zhat[zr + 3584 + o]  = f[6];
    }
}

// ---------------------------------------------------------------------------
// Final: iFFT of FC planes + bias + residual -> out
// ---------------------------------------------------------------------------
__global__ __launch_bounds__(256)
void fc_ifft_kernel(const float* __restrict__ Yf, const float* __restrict__ bias,
                    const float* __restrict__ resid, float* __restrict__ out) {
    int e = blockIdx.x * blockDim.x + threadIdx.x;
    int b = e >> 7, o = e & 127;
    const float* S = Yf + (size_t)b * 1024;
    float f[8], y[8];
#pragma unroll
    for (int p = 0; p < 8; p++) f[p] = S[p * 128 + o];
    ifft8(f, y);
    float bb = bias[o];
    size_t nb = (size_t)b * 1024 + o * 8;
    const float* rp = resid + nb;
    float* op = out + nb;
#pragma unroll
    for (int g = 0; g < 8; g++) op[g] = y[g] + bb + rp[g];
}

// ---------------------------------------------------------------------------
// Launch
// ---------------------------------------------------------------------------
extern "C" void kernel_launch(void* const* d_in, const int* in_sizes, int n_in,
                              void* d_out, int out_size) {
    const float* q    = (const float*)d_in[0];
    const float* k    = (const float*)d_in[1];
    const float* v    = (const float*)d_in[2];
    const float* w_q  = (const float*)d_in[3];
    const float* b_q  = (const float*)d_in[4];
    const float* w_k  = (const float*)d_in[5];
    const float* b_k  = (const float*)d_in[6];
    const float* w_v  = (const float*)d_in[7];
    const float* b_v  = (const float*)d_in[8];
    const float* w_fc = (const float*)d_in[9];
    const float* b_fc = (const float*)d_in[10];

    float* out = (float*)d_out;
    const size_t OUT_ELEMS  = (size_t)BATCH * CDIM;
    const size_t ATTN_ELEMS = (size_t)BATCH * 512;

    float *Xq, *Xk, *Xv, *Wq, *Wk, *Wv, *Wf, *Yq, *Yk, *Yv, *Zh, *Yf, *attnDummy;
    cudaGetSymbolAddress((void**)&Xq, g_Xq);
    cudaGetSymbolAddress((void**)&Xk, g_Xk);
    cudaGetSymbolAddress((void**)&Xv, g_Xv);
    cudaGetSymbolAddress((void**)&Wq, g_Wq);
    cudaGetSymbolAddress((void**)&Wk, g_Wk);
    cudaGetSymbolAddress((void**)&Wv, g_Wv);
    cudaGetSymbolAddress((void**)&Wf, g_Wf);
    cudaGetSymbolAddress((void**)&Yq, g_Yq);
    cudaGetSymbolAddress((void**)&Yk, g_Yk);
    cudaGetSymbolAddress((void**)&Yv, g_Yv);
    cudaGetSymbolAddress((void**)&Zh, g_Zh);
    cudaGetSymbolAddress((void**)&Yf, g_Yf);
    cudaGetSymbolAddress((void**)&attnDummy, g_attn_dummy);

    float* attn_out = ((size_t)out_size >= OUT_ELEMS + ATTN_ELEMS)
                          ? (out + OUT_ELEMS) : attnDummy;

    // 1) forward FFT of activations (fused) and weights (fused)
    dim3 ga(BATCH / 2, 3);
    act_fft3_kernel<<<ga, 256>>>(q, k, v, Xq, Xk, Xv);
    dim3 gw(256, 4);
    wfft4_kernel<<<gw, 256>>>(w_q, w_k, w_v, w_fc, Wq, Wk, Wv, Wf);

    // 2) frequency-domain projection GEMMs (8 jobs in grid.z)
    cudaFuncSetAttribute(gemm_freq, cudaFuncAttributeMaxDynamicSharedMemorySize,
                         GEMM_SMEM_BYTES);
    dim3 gp(4, BATCH / TM, 8);
    gemm_freq<<<gp, 256, GEMM_SMEM_BYTES>>>(Xq, Wq, Yq, 1024, 4096, 0);
    gemm_freq<<<gp, 256, GEMM_SMEM_BYTES>>>(Xk, Wk, Yk, 1024, 4096, 0);
    gemm_freq<<<gp, 256, GEMM_SMEM_BYTES>>>(Xv, Wv, Yv, 1024, 4096, 0);

    // 3) attention (iFFT staging + bias; FFT epilogue -> Zhat)
    cudaFuncSetAttribute(attn_freq_kernel, cudaFuncAttributeMaxDynamicSharedMemorySize,
                         ATTN_SMEM);
    attn_freq_kernel<<<BATCH, 256, ATTN_SMEM>>>(Yq, Yk, Yv, b_q, b_k, b_v,
                                                Zh, attn_out);

    // 4) frequency-domain FC GEMM
    dim3 gf(1, BATCH / TM, 8);
    gemm_freq<<<gf, 256, GEMM_SMEM_BYTES>>>(Zh, Wf, Yf, 4096, 1024, 1);

    // 5) inverse FFT + bias + residual
    fc_ifft_kernel<<<BATCH * 128 / 256, 256>>>(Yf, b_fc, q, out);
}

// round 12
// speedup vs baseline: 1.2430x; 1.2430x over previous
#include <cuda_runtime.h>
#include <cstdint>

// ---------------------------------------------------------------------------
// Problem constants
// ---------------------------------------------------------------------------
#define BATCH   8192
#define CDIM    1024

// ---------------------------------------------------------------------------
// Device scratch (layouts identical to round-10 passing kernel)
// ---------------------------------------------------------------------------
__device__ float g_Xq[(size_t)BATCH * 1024u];
__device__ float g_Xk[(size_t)BATCH * 1024u];
__device__ float g_Xv[(size_t)BATCH * 1024u];
__device__ float g_Wq[917504u];          // 14 * 512*128
__device__ float g_Wk[917504u];
__device__ float g_Wv[917504u];
__device__ float g_Wf[917504u];          // 14 * 128*512
__device__ float g_Yq[(size_t)BATCH * 4096u];
__device__ float g_Yk[(size_t)BATCH * 4096u];
__device__ float g_Yv[(size_t)BATCH * 4096u];
__device__ float g_Zh[(size_t)BATCH * 4096u];
__device__ float g_Yf[(size_t)BATCH * 1024u];
__device__ float g_attn_dummy[(size_t)BATCH * 512u];

// ---------------------------------------------------------------------------
// GEMM job tables (mode 0 = projection, 1 = fc)
// ---------------------------------------------------------------------------
__constant__ int c_aoff[2][8] = {{0, 256, 256, 512, 512, 768, 768, 128},
                                 {0, 1024, 1024, 2048, 2048, 3072, 3072, 512}};
__constant__ int c_kk[2][8]   = {{128, 256, 256, 256, 256, 256, 256, 128},
                                 {512, 1024, 1024, 1024, 1024, 1024, 1024, 512}};
__constant__ int c_woff[8]    = {0, 65536, 196608, 327680, 458752, 589824, 720896, 851968};
__constant__ int c_coff[2][8] = {{0, 512, 1024, 1536, 2048, 2560, 3072, 3584},
                                 {0, 128, 256, 384, 512, 640, 768, 896}};

// ---------------------------------------------------------------------------
// FFT8 helpers
// ---------------------------------------------------------------------------
#define C1F 0.70710678118654752f

__device__ __forceinline__ void fft8(const float* x, float* f) {
    float t0 = x[0] + x[4], t4 = x[0] - x[4];
    float t1 = x[1] + x[5], t5 = x[1] - x[5];
    float t2 = x[2] + x[6], t6 = x[2] - x[6];
    float t3 = x[3] + x[7], t7 = x[3] - x[7];
    f[0] = t0 + t1 + t2 + t3;
    f[7] = t0 - t1 + t2 - t3;
    f[3] = t0 - t2;
    f[4] = t3 - t1;
    float a = C1F * (t5 - t7), b = C1F * (t5 + t7);
    f[1] = t4 + a;
    f[2] = -t6 - b;
    f[5] = t4 - a;
    f[6] = t6 - b;
}

__device__ __forceinline__ void ifft8(const float* f, float* y) {
    float u0 = 0.5f * (f[0] + f[7]);
    float u1 = 0.5f * (f[0] - f[7]);
    float t0 = 0.5f * (u0 + f[3]);
    float t2 = 0.5f * (u0 - f[3]);
    float t3 = 0.5f * (u1 + f[4]);
    float t1 = 0.5f * (u1 - f[4]);
    float t4 = 0.5f * (f[1] + f[5]);
    float d57 = (f[1] - f[5]) * (0.5f / C1F);
    float t6 = 0.5f * (f[6] - f[2]);
    float s57 = -(f[2] + f[6]) * (0.5f / C1F);
    float t5 = 0.5f * (s57 + d57);
    float t7 = 0.5f * (s57 - d57);
    y[0] = 0.5f * (t0 + t4);  y[4] = 0.5f * (t0 - t4);
    y[1] = 0.5f * (t1 + t5);  y[5] = 0.5f * (t1 - t5);
    y[2] = 0.5f * (t2 + t6);  y[6] = 0.5f * (t2 - t6);
    y[3] = 0.5f * (t3 + t7);  y[7] = 0.5f * (t3 - t7);
}

// ---------------------------------------------------------------------------
// Fused activation forward FFT for q,k,v (grid.y selects tensor)
// ---------------------------------------------------------------------------
__global__ __launch_bounds__(256)
void act_fft3_kernel(const float* __restrict__ x0, const float* __restrict__ x1,
                     const float* __restrict__ x2,
                     float* __restrict__ h0, float* __restrict__ h1,
                     float* __restrict__ h2) {
    __shared__ float s[2 * 1152];
    int blk = blockIdx.x, tid = threadIdx.x;
    const float* x = (blockIdx.y == 0) ? x0 : (blockIdx.y == 1) ? x1 : x2;
    float* xh      = (blockIdx.y == 0) ? h0 : (blockIdx.y == 1) ? h1 : h2;
    size_t base = (size_t)blk * 2048;
#pragma unroll
    for (int i = 0; i < 2; i++) {
        int e = tid + i * 256;
        int row = e >> 8, c4 = e & 255;
        float4 v = reinterpret_cast<const float4*>(x + base + row * 1024)[c4];
        int k = c4 * 4;
        float* d = s + row * 1152 + k + (k >> 3);
        d[0] = v.x; d[1] = v.y; d[2] = v.z; d[3] = v.w;
    }
    __syncthreads();
    int row = tid >> 7, o = tid & 127;
    float xx[8], f[8];
    const float* sp = s + row * 1152 + o * 9;
#pragma unroll
    for (int j = 0; j < 8; j++) xx[j] = sp[j];
    fft8(xx, f);
    size_t ob = (size_t)(blk * 2 + row) * 1024;
    xh[ob + o]       = f[0];
    xh[ob + 128 + o] = f[7];
    xh[ob + 256 + o] = f[1];
    xh[ob + 384 + o] = f[2];
    xh[ob + 512 + o] = f[3];
    xh[ob + 640 + o] = f[4];
    xh[ob + 768 + o] = f[5];
    xh[ob + 896 + o] = f[6];
}

// ---------------------------------------------------------------------------
// Fused weight FFT + job stacking for all 4 weights (grid.y selects weight)
// ---------------------------------------------------------------------------
__global__ void wfft4_kernel(const float* __restrict__ w0, const float* __restrict__ w1,
                             const float* __restrict__ w2, const float* __restrict__ w3,
                             float* __restrict__ s0, float* __restrict__ s1,
                             float* __restrict__ s2, float* __restrict__ s3) {
    int which = blockIdx.y;
    const float* w = (which == 0) ? w0 : (which == 1) ? w1 : (which == 2) ? w2 : w3;
    float* ws      = (which == 0) ? s0 : (which == 1) ? s1 : (which == 2) ? s2 : s3;
    int I = (which == 3) ? 512 : 128;
    int e = blockIdx.x * blockDim.x + threadIdx.x;   // e < 65536 = O*I
    int o = e / I, i = e - o * I;
    float xx[8], f[8];
    const float* wp = w + (size_t)e * 8;
#pragma unroll
    for (int j = 0; j < 8; j++) xx[j] = wp[j];
    fft8(xx, f);
    const size_t OI = 65536u;
    ws[e] = f[0];
    ws[13 * OI + e] = f[7];
#pragma unroll
    for (int m = 1; m <= 3; m++) {
        float re = f[2 * m - 1], im = f[2 * m];
        size_t j1 = OI * (size_t)(4 * m - 3);
        size_t j2 = OI * (size_t)(4 * m - 1);
        size_t rb = (size_t)o * 2 * I + i;
        ws[j1 + rb]     = re;
        ws[j1 + rb + I] = -im;
        ws[j2 + rb]     = im;
        ws[j2 + rb + I] = re;
    }
}

// ---------------------------------------------------------------------------
// GEMM (R10-proven body, UNCHANGED): C = A * B^T per frequency job.
// grid.z selects (tensor, job): proj mode grid.z=24, fc mode grid.z=8.
// ---------------------------------------------------------------------------
#define TM 128
#define TN 128
#define TK 32
#define PADK 40
#define TILE_H (128 * PADK)
#define STAGE_H (4 * TILE_H)
#define GEMM_SMEM_BYTES (2 * STAGE_H * 2)   // 81,920 B

__device__ __forceinline__ void mma16816(float* c, const uint32_t* a, const uint32_t* b) {
    asm volatile(
        "mma.sync.aligned.m16n8k16.row.col.f32.bf16.bf16.f32 "
        "{%0,%1,%2,%3}, {%4,%5,%6,%7}, {%8,%9}, {%0,%1,%2,%3};"
        : "+f"(c[0]), "+f"(c[1]), "+f"(c[2]), "+f"(c[3])
        : "r"(a[0]), "r"(a[1]), "r"(a[2]), "r"(a[3]), "r"(b[0]), "r"(b[1]));
}

__device__ __forceinline__ void split_sts(float4 v, uint16_t* ph, uint16_t* pl) {
    uint32_t ux = __float_as_uint(v.x), uy = __float_as_uint(v.y);
    uint32_t uz = __float_as_uint(v.z), uw = __float_as_uint(v.w);
    uint32_t h0 = __byte_perm(ux, uy, 0x7632);
    uint32_t h1 = __byte_perm(uz, uw, 0x7632);
    float lx = v.x - __uint_as_float(ux & 0xffff0000u);
    float ly = v.y - __uint_as_float(uy & 0xffff0000u);
    float lz = v.z - __uint_as_float(uz & 0xffff0000u);
    float lw = v.w - __uint_as_float(uw & 0xffff0000u);
    uint32_t l0, l1;
    asm("cvt.rn.bf16x2.f32 %0, %1, %2;" : "=r"(l0) : "f"(ly), "f"(lx));
    asm("cvt.rn.bf16x2.f32 %0, %1, %2;" : "=r"(l1) : "f"(lw), "f"(lz));
    uint2 hv; hv.x = h0; hv.y = h1;
    uint2 lv; lv.x = l0; lv.y = l1;
    *reinterpret_cast<uint2*>(ph) = hv;
    *reinterpret_cast<uint2*>(pl) = lv;
}

__global__ __launch_bounds__(256)
void gemm_freq(const float* __restrict__ X0, const float* __restrict__ X1,
               const float* __restrict__ X2,
               const float* __restrict__ W0, const float* __restrict__ W1,
               const float* __restrict__ W2,
               float* __restrict__ C0, float* __restrict__ C1,
               float* __restrict__ C2,
               int lda, int ldc, int mode)
{
    extern __shared__ uint16_t sm16[];

    const int zt   = blockIdx.z;
    const int z    = zt & 7;
    const int t3   = zt >> 3;
    const float* Xh = (t3 == 0) ? X0 : (t3 == 1) ? X1 : X2;
    const float* Ws = (t3 == 0) ? W0 : (t3 == 1) ? W1 : W2;
    float*       Ch = (t3 == 0) ? C0 : (t3 == 1) ? C1 : C2;

    const int K    = c_kk[mode][z];
    const int aoff = c_aoff[mode][z];
    const int coff = c_coff[mode][z];

    const int tid  = threadIdx.x;
    const int wid  = tid >> 5, lane = tid & 31;
    const int wm   = wid >> 2, wn = wid & 3;
    const int q    = lane >> 2;
    const int t4   = (lane & 3) * 2;

    const size_t m0 = (size_t)blockIdx.y * TM;
    const float* Ab = Xh + m0 * (size_t)lda + aoff;
    const float* Bb = Ws + (size_t)c_woff[z] + (size_t)blockIdx.x * 128 * (size_t)K;

    float acc[4][4][4];
#pragma unroll
    for (int i = 0; i < 4; i++)
#pragma unroll
        for (int j = 0; j < 4; j++)
#pragma unroll
            for (int r = 0; r < 4; r++) acc[i][j][r] = 0.f;

    float4 ra[4], rb[4];
#pragma unroll
    for (int i = 0; i < 4; i++) {
        int e = tid + i * 256, row = e >> 3, k4 = (e & 7) * 4;
        ra[i] = *reinterpret_cast<const float4*>(Ab + (size_t)row * lda + k4);
        rb[i] = *reinterpret_cast<const float4*>(Bb + (size_t)row * K + k4);
    }

    const int NC = K / TK;
    for (int c = 0; c < NC; c++) {
        const int s = c & 1;
        uint16_t* Ah = sm16 + s * STAGE_H;
        uint16_t* Al = Ah + TILE_H;
        uint16_t* Bh = Ah + 2 * TILE_H;
        uint16_t* Bl = Ah + 3 * TILE_H;

#pragma unroll
        for (int i = 0; i < 4; i++) {
            int e = tid + i * 256, row = e >> 3, k4 = (e & 7) * 4;
            int off = row * PADK + k4;
            split_sts(ra[i], Ah + off, Al + off);
            split_sts(rb[i], Bh + off, Bl + off);
        }
        __syncthreads();

        if (c + 1 < NC) {
            int k0 = (c + 1) * TK;
#pragma unroll
            for (int i = 0; i < 4; i++) {
                int e = tid + i * 256, row = e >> 3, k4 = (e & 7) * 4;
                ra[i] = *reinterpret_cast<const float4*>(Ab + (size_t)row * lda + k0 + k4);
                rb[i] = *reinterpret_cast<const float4*>(Bb + (size_t)row * K + k0 + k4);
            }
        }

#pragma unroll
        for (int ks = 0; ks < 2; ks++) {
            const int kb = ks * 16;
            uint32_t ah[4][4], al[4][4], bh[4][2], bl[4][2];
#pragma unroll
            for (int i = 0; i < 4; i++) {
                int r = wm * 64 + i * 16 + q;
                int o00 = r * PADK + kb + t4;
                int o10 = (r + 8) * PADK + kb + t4;
                ah[i][0] = *reinterpret_cast<const uint32_t*>(Ah + o00);
                ah[i][1] = *reinterpret_cast<const uint32_t*>(Ah + o10);
                ah[i][2] = *reinterpret_cast<const uint32_t*>(Ah + o00 + 8);
                ah[i][3] = *reinterpret_cast<const uint32_t*>(Ah + o10 + 8);
                al[i][0] = *reinterpret_cast<const uint32_t*>(Al + o00);
                al[i][1] = *reinterpret_cast<const uint32_t*>(Al + o10);
                al[i][2] = *reinterpret_cast<const uint32_t*>(Al + o00 + 8);
                al[i][3] = *reinterpret_cast<const uint32_t*>(Al + o10 + 8);
            }
#pragma unroll
            for (int j = 0; j < 4; j++) {
                int r = wn * 32 + j * 8 + q;
                int o0 = r * PADK + kb + t4;
                bh[j][0] = *reinterpret_cast<const uint32_t*>(Bh + o0);
                bh[j][1] = *reinterpret_cast<const uint32_t*>(Bh + o0 + 8);
                bl[j][0] = *reinterpret_cast<const uint32_t*>(Bl + o0);
                bl[j][1] = *reinterpret_cast<const uint32_t*>(Bl + o0 + 8);
            }
#pragma unroll
            for (int i = 0; i < 4; i++)
#pragma unroll
                for (int j = 0; j < 4; j++) mma16816(acc[i][j], ah[i], bh[j]);
#pragma unroll
            for (int i = 0; i < 4; i++)
#pragma unroll
                for (int j = 0; j < 4; j++) mma16816(acc[i][j], al[i], bh[j]);
#pragma unroll
            for (int i = 0; i < 4; i++)
#pragma unroll
                for (int j = 0; j < 4; j++) mma16816(acc[i][j], ah[i], bl[j]);
        }
        __syncthreads();
    }

    const int nbase = coff + blockIdx.x * 128;
#pragma unroll
    for (int i = 0; i < 4; i++) {
        size_t r = m0 + wm * 64 + i * 16 + q;
#pragma unroll
        for (int j = 0; j < 4; j++) {
            int cl = nbase + wn * 32 + j * 8 + t4;
            float2 v0, v1;
            v0.x = acc[i][j][0]; v0.y = acc[i][j][1];
            v1.x = acc[i][j][2]; v1.y = acc[i][j][3];
            *reinterpret_cast<float2*>(Ch + r * ldc + cl)       = v0;
            *reinterpret_cast<float2*>(Ch + (r + 8) * ldc + cl) = v1;
        }
    }
}

// ---------------------------------------------------------------------------
// Attention (identical to round-10 passing kernel)
// ---------------------------------------------------------------------------
#define ROWSTR 516
#define ZBUF_OFF (24 * ROWSTR)
#define ATTN_SMEM ((24 * ROWSTR + 4608) * 4)

__global__ __launch_bounds__(256)
void attn_freq_kernel(const float* __restrict__ Yq, const float* __restrict__ Yk,
                      const float* __restrict__ Yv,
                      const float* __restrict__ bq, const float* __restrict__ bk,
                      const float* __restrict__ bv,
                      float* __restrict__ Zhat, float* __restrict__ attn_out)
{
    extern __shared__ float sm[];
    float* sQ = sm;
    float* sK = sm + 8 * ROWSTR;
    float* sV = sm + 16 * ROWSTR;
    float* zb = sm + ZBUF_OFF;

    int b   = blockIdx.x;
    int tid = threadIdx.x;

    const float* srcs[3] = {Yq + (size_t)b * 4096, Yk + (size_t)b * 4096,
                            Yv + (size_t)b * 4096};
    const float* bss[3]  = {bq, bk, bv};
    float* dsts[3] = {sQ, sK, sV};
#pragma unroll
    for (int t3 = 0; t3 < 3; t3++) {
        const float* S = srcs[t3];
        const float* Bp = bss[t3];
        float* D = dsts[t3];
        for (int o = tid; o < 512; o += 256) {
            float f[8], y[8];
#pragma unroll
            for (int p = 0; p < 8; p++) f[p] = S[p * 512 + o];
            ifft8(f, y);
            float bias = Bp[o];
            float* dp = D + (o >> 6) * ROWSTR + (o & 63) * 8;
#pragma unroll
            for (int g = 0; g < 8; g++) dp[g] = y[g] + bias;
        }
    }
    __syncthreads();

    int w    = tid >> 5;
    int lane = tid & 31;
    int base = w * 64;
    int g1a  = lane >> 3;
    int g2   = lane & 7;
    int g1b  = g1a + 4;

    const float* qa = sQ + g1a * ROWSTR + base;
    const float* qb = sQ + g1b * ROWSTR + base;
    const float* kr = sK + g2  * ROWSTR + base;
    float s0 = 0.f, s1 = 0.f;
#pragma unroll 8
    for (int d = 0; d < 64; d++) {
        float kv = kr[d];
        s0 = fmaf(qa[d], kv, s0);
        s1 = fmaf(qb[d], kv, s1);
    }
    s0 *= 0.125f; s1 *= 0.125f;

    float m0 = s0, m1 = s1;
#pragma unroll
    for (int off = 4; off; off >>= 1) {
        m0 = fmaxf(m0, __shfl_xor_sync(0xffffffffu, m0, off));
        m1 = fmaxf(m1, __shfl_xor_sync(0xffffffffu, m1, off));
    }
    float e0 = __expf(s0 - m0), e1 = __expf(s1 - m1);
    float z0 = e0, z1 = e1;
#pragma unroll
    for (int off = 4; off; off >>= 1) {
        z0 += __shfl_xor_sync(0xffffffffu, z0, off);
        z1 += __shfl_xor_sync(0xffffffffu, z1, off);
    }
    float a0 = e0 / z0, a1 = e1 / z1;

    attn_out[(size_t)b * 512 + base + lane]      = a0;
    attn_out[(size_t)b * 512 + base + 32 + lane] = a1;

    __syncwarp();
    sQ[g1a * ROWSTR + base + g2] = a0;
    sQ[g1b * ROWSTR + base + g2] = a1;
    __syncwarp();

#pragma unroll
    for (int g1 = 0; g1 < 8; g1++) {
        const float* ar = sQ + g1 * ROWSTR + base;
        float acc0 = 0.f, acc1 = 0.f;
#pragma unroll
        for (int j = 0; j < 8; j++) {
            float a = ar[j];
            acc0 = fmaf(a, sV[j * ROWSTR + base + lane],      acc0);
            acc1 = fmaf(a, sV[j * ROWSTR + base + 32 + lane], acc1);
        }
        int n0 = g1 * 512 + base + lane;
        int n1 = n0 + 32;
        zb[n0 + (n0 >> 3)] = acc0;
        zb[n1 + (n1 >> 3)] = acc1;
    }
    __syncthreads();

    size_t zr = (size_t)b * 4096;
    for (int o = tid; o < 512; o += 256) {
        float xx[8], f[8];
        const float* zp = zb + o * 9;
#pragma unroll
        for (int j = 0; j < 8; j++) xx[j] = zp[j];
        fft8(xx, f);
        Zhat[zr + o]         = f[0];
        Zhat[zr + 512 + o]   = f[7];
        Zhat[zr + 1024 + o]  = f[1];
        Zhat[zr + 1536 + o]  = f[2];
        Zhat[zr + 2048 + o]  = f[3];
        Zhat[zr + 2560 + o]  = f[4];
        Zhat[zr + 3072 + o]  = f[5];
        Zhat[zr + 3584 + o]  = f[6];
    }
}

// ---------------------------------------------------------------------------
// Final: iFFT of FC planes + bias + residual -> out
// ---------------------------------------------------------------------------
__global__ __launch_bounds__(256)
void fc_ifft_kernel(const float* __restrict__ Yf, const float* __restrict__ bias,
                    const float* __restrict__ resid, float* __restrict__ out) {
    int e = blockIdx.x * blockDim.x + threadIdx.x;
    int b = e >> 7, o = e & 127;
    const float* S = Yf + (size_t)b * 1024;
    float f[8], y[8];
#pragma unroll
    for (int p = 0; p < 8; p++) f[p] = S[p * 128 + o];
    ifft8(f, y);
    float bb = bias[o];
    size_t nb = (size_t)b * 1024 + o * 8;
    const float* rp = resid + nb;
    float* op = out + nb;
#pragma unroll
    for (int g = 0; g < 8; g++) op[g] = y[g] + bb + rp[g];
}

// ---------------------------------------------------------------------------
// Launch
// ---------------------------------------------------------------------------
extern "C" void kernel_launch(void* const* d_in, const int* in_sizes, int n_in,
                              void* d_out, int out_size) {
    const float* q    = (const float*)d_in[0];
    const float* k    = (const float*)d_in[1];
    const float* v    = (const float*)d_in[2];
    const float* w_q  = (const float*)d_in[3];
    const float* b_q  = (const float*)d_in[4];
    const float* w_k  = (const float*)d_in[5];
    const float* b_k  = (const float*)d_in[6];
    const float* w_v  = (const float*)d_in[7];
    const float* b_v  = (const float*)d_in[8];
    const float* w_fc = (const float*)d_in[9];
    const float* b_fc = (const float*)d_in[10];

    float* out = (float*)d_out;
    const size_t OUT_ELEMS  = (size_t)BATCH * CDIM;
    const size_t ATTN_ELEMS = (size_t)BATCH * 512;

    float *Xq, *Xk, *Xv, *Wq, *Wk, *Wv, *Wf, *Yq, *Yk, *Yv, *Zh, *Yf, *attnDummy;
    cudaGetSymbolAddress((void**)&Xq, g_Xq);
    cudaGetSymbolAddress((void**)&Xk, g_Xk);
    cudaGetSymbolAddress((void**)&Xv, g_Xv);
    cudaGetSymbolAddress((void**)&Wq, g_Wq);
    cudaGetSymbolAddress((void**)&Wk, g_Wk);
    cudaGetSymbolAddress((void**)&Wv, g_Wv);
    cudaGetSymbolAddress((void**)&Wf, g_Wf);
    cudaGetSymbolAddress((void**)&Yq, g_Yq);
    cudaGetSymbolAddress((void**)&Yk, g_Yk);
    cudaGetSymbolAddress((void**)&Yv, g_Yv);
    cudaGetSymbolAddress((void**)&Zh, g_Zh);
    cudaGetSymbolAddress((void**)&Yf, g_Yf);
    cudaGetSymbolAddress((void**)&attnDummy, g_attn_dummy);

    float* attn_out = ((size_t)out_size >= OUT_ELEMS + ATTN_ELEMS)
                          ? (out + OUT_ELEMS) : attnDummy;

    // 1) forward FFT of activations (fused) and weights (fused)
    dim3 ga(BATCH / 2, 3);
    act_fft3_kernel<<<ga, 256>>>(q, k, v, Xq, Xk, Xv);
    dim3 gw(256, 4);
    wfft4_kernel<<<gw, 256>>>(w_q, w_k, w_v, w_fc, Wq, Wk, Wv, Wf);

    // 2) all 3 projection GEMMs in ONE launch (grid.z = 3 tensors x 8 jobs)
    cudaFuncSetAttribute(gemm_freq, cudaFuncAttributeMaxDynamicSharedMemorySize,
                         GEMM_SMEM_BYTES);
    dim3 gp(4, BATCH / TM, 24);
    gemm_freq<<<gp, 256, GEMM_SMEM_BYTES>>>(Xq, Xk, Xv, Wq, Wk, Wv,
                                            Yq, Yk, Yv, 1024, 4096, 0);

    // 3) attention (iFFT staging + bias; FFT epilogue -> Zhat)
    cudaFuncSetAttribute(attn_freq_kernel, cudaFuncAttributeMaxDynamicSharedMemorySize,
                         ATTN_SMEM);
    attn_freq_kernel<<<BATCH, 256, ATTN_SMEM>>>(Yq, Yk, Yv, b_q, b_k, b_v,
                                                Zh, attn_out);

    // 4) frequency-domain FC GEMM (single tensor; grid.z = 8 jobs)
    dim3 gf(1, BATCH / TM, 8);
    gemm_freq<<<gf, 256, GEMM_SMEM_BYTES>>>(Zh, Zh, Zh, Wf, Wf, Wf,
                                            Yf, Yf, Yf, 4096, 1024, 1);

    // 5) inverse FFT + bias + residual
    fc_ifft_kernel<<<BATCH * 128 / 256, 256>>>(Yf, b_fc, q, out);
}

// round 13
// speedup vs baseline: 1.2454x; 1.0019x over previous
#include <cuda_runtime.h>
#include <cstdint>

// ---------------------------------------------------------------------------
// Problem constants
// ---------------------------------------------------------------------------
#define BATCH   8192
#define CDIM    1024

// ---------------------------------------------------------------------------
// Device scratch (layouts identical to round-12 passing kernel)
// ---------------------------------------------------------------------------
__device__ float g_Xq[(size_t)BATCH * 1024u];
__device__ float g_Xk[(size_t)BATCH * 1024u];
__device__ float g_Xv[(size_t)BATCH * 1024u];
__device__ float g_Wq[917504u];          // 14 * 512*128
__device__ float g_Wk[917504u];
__device__ float g_Wv[917504u];
__device__ float g_Wf[917504u];          // 14 * 128*512
__device__ float g_Yq[(size_t)BATCH * 4096u];
__device__ float g_Yk[(size_t)BATCH * 4096u];
__device__ float g_Yv[(size_t)BATCH * 4096u];
__device__ float g_Zh[(size_t)BATCH * 4096u];
__device__ float g_Yf[(size_t)BATCH * 1024u];
__device__ float g_attn_dummy[(size_t)BATCH * 512u];

// ---------------------------------------------------------------------------
// GEMM job tables (mode 0 = projection, 1 = fc)
// ---------------------------------------------------------------------------
__constant__ int c_aoff[2][8] = {{0, 256, 256, 512, 512, 768, 768, 128},
                                 {0, 1024, 1024, 2048, 2048, 3072, 3072, 512}};
__constant__ int c_kk[2][8]   = {{128, 256, 256, 256, 256, 256, 256, 128},
                                 {512, 1024, 1024, 1024, 1024, 1024, 1024, 512}};
__constant__ int c_woff[8]    = {0, 65536, 196608, 327680, 458752, 589824, 720896, 851968};
__constant__ int c_coff[2][8] = {{0, 512, 1024, 1536, 2048, 2560, 3072, 3584},
                                 {0, 128, 256, 384, 512, 640, 768, 896}};

// ---------------------------------------------------------------------------
// FFT8 helpers
// ---------------------------------------------------------------------------
#define C1F 0.70710678118654752f

__device__ __forceinline__ void fft8(const float* x, float* f) {
    float t0 = x[0] + x[4], t4 = x[0] - x[4];
    float t1 = x[1] + x[5], t5 = x[1] - x[5];
    float t2 = x[2] + x[6], t6 = x[2] - x[6];
    float t3 = x[3] + x[7], t7 = x[3] - x[7];
    f[0] = t0 + t1 + t2 + t3;
    f[7] = t0 - t1 + t2 - t3;
    f[3] = t0 - t2;
    f[4] = t3 - t1;
    float a = C1F * (t5 - t7), b = C1F * (t5 + t7);
    f[1] = t4 + a;
    f[2] = -t6 - b;
    f[5] = t4 - a;
    f[6] = t6 - b;
}

__device__ __forceinline__ void ifft8(const float* f, float* y) {
    float u0 = 0.5f * (f[0] + f[7]);
    float u1 = 0.5f * (f[0] - f[7]);
    float t0 = 0.5f * (u0 + f[3]);
    float t2 = 0.5f * (u0 - f[3]);
    float t3 = 0.5f * (u1 + f[4]);
    float t1 = 0.5f * (u1 - f[4]);
    float t4 = 0.5f * (f[1] + f[5]);
    float d57 = (f[1] - f[5]) * (0.5f / C1F);
    float t6 = 0.5f * (f[6] - f[2]);
    float s57 = -(f[2] + f[6]) * (0.5f / C1F);
    float t5 = 0.5f * (s57 + d57);
    float t7 = 0.5f * (s57 - d57);
    y[0] = 0.5f * (t0 + t4);  y[4] = 0.5f * (t0 - t4);
    y[1] = 0.5f * (t1 + t5);  y[5] = 0.5f * (t1 - t5);
    y[2] = 0.5f * (t2 + t6);  y[6] = 0.5f * (t2 - t6);
    y[3] = 0.5f * (t3 + t7);  y[7] = 0.5f * (t3 - t7);
}

// ---------------------------------------------------------------------------
// Fused activation forward FFT for q,k,v (grid.y selects tensor)
// ---------------------------------------------------------------------------
__global__ __launch_bounds__(256)
void act_fft3_kernel(const float* __restrict__ x0, const float* __restrict__ x1,
                     const float* __restrict__ x2,
                     float* __restrict__ h0, float* __restrict__ h1,
                     float* __restrict__ h2) {
    __shared__ float s[2 * 1152];
    int blk = blockIdx.x, tid = threadIdx.x;
    const float* x = (blockIdx.y == 0) ? x0 : (blockIdx.y == 1) ? x1 : x2;
    float* xh      = (blockIdx.y == 0) ? h0 : (blockIdx.y == 1) ? h1 : h2;
    size_t base = (size_t)blk * 2048;
#pragma unroll
    for (int i = 0; i < 2; i++) {
        int e = tid + i * 256;
        int row = e >> 8, c4 = e & 255;
        float4 v = reinterpret_cast<const float4*>(x + base + row * 1024)[c4];
        int k = c4 * 4;
        float* d = s + row * 1152 + k + (k >> 3);
        d[0] = v.x; d[1] = v.y; d[2] = v.z; d[3] = v.w;
    }
    __syncthreads();
    int row = tid >> 7, o = tid & 127;
    float xx[8], f[8];
    const float* sp = s + row * 1152 + o * 9;
#pragma unroll
    for (int j = 0; j < 8; j++) xx[j] = sp[j];
    fft8(xx, f);
    size_t ob = (size_t)(blk * 2 + row) * 1024;
    xh[ob + o]       = f[0];
    xh[ob + 128 + o] = f[7];
    xh[ob + 256 + o] = f[1];
    xh[ob + 384 + o] = f[2];
    xh[ob + 512 + o] = f[3];
    xh[ob + 640 + o] = f[4];
    xh[ob + 768 + o] = f[5];
    xh[ob + 896 + o] = f[6];
}

// ---------------------------------------------------------------------------
// Fused weight FFT + job stacking for all 4 weights (grid.y selects weight)
// ---------------------------------------------------------------------------
__global__ void wfft4_kernel(const float* __restrict__ w0, const float* __restrict__ w1,
                             const float* __restrict__ w2, const float* __restrict__ w3,
                             float* __restrict__ s0, float* __restrict__ s1,
                             float* __restrict__ s2, float* __restrict__ s3) {
    int which = blockIdx.y;
    const float* w = (which == 0) ? w0 : (which == 1) ? w1 : (which == 2) ? w2 : w3;
    float* ws      = (which == 0) ? s0 : (which == 1) ? s1 : (which == 2) ? s2 : s3;
    int I = (which == 3) ? 512 : 128;
    int e = blockIdx.x * blockDim.x + threadIdx.x;   // e < 65536 = O*I
    int o = e / I, i = e - o * I;
    float xx[8], f[8];
    const float* wp = w + (size_t)e * 8;
#pragma unroll
    for (int j = 0; j < 8; j++) xx[j] = wp[j];
    fft8(xx, f);
    const size_t OI = 65536u;
    ws[e] = f[0];
    ws[13 * OI + e] = f[7];
#pragma unroll
    for (int m = 1; m <= 3; m++) {
        float re = f[2 * m - 1], im = f[2 * m];
        size_t j1 = OI * (size_t)(4 * m - 3);
        size_t j2 = OI * (size_t)(4 * m - 1);
        size_t rb = (size_t)o * 2 * I + i;
        ws[j1 + rb]     = re;
        ws[j1 + rb + I] = -im;
        ws[j2 + rb]     = im;
        ws[j2 + rb + I] = re;
    }
}

// ---------------------------------------------------------------------------
// GEMM (R10-proven body, UNCHANGED)
// ---------------------------------------------------------------------------
#define TM 128
#define TN 128
#define TK 32
#define PADK 40
#define TILE_H (128 * PADK)
#define STAGE_H (4 * TILE_H)
#define GEMM_SMEM_BYTES (2 * STAGE_H * 2)   // 81,920 B

__device__ __forceinline__ void mma16816(float* c, const uint32_t* a, const uint32_t* b) {
    asm volatile(
        "mma.sync.aligned.m16n8k16.row.col.f32.bf16.bf16.f32 "
        "{%0,%1,%2,%3}, {%4,%5,%6,%7}, {%8,%9}, {%0,%1,%2,%3};"
        : "+f"(c[0]), "+f"(c[1]), "+f"(c[2]), "+f"(c[3])
        : "r"(a[0]), "r"(a[1]), "r"(a[2]), "r"(a[3]), "r"(b[0]), "r"(b[1]));
}

__device__ __forceinline__ void split_sts(float4 v, uint16_t* ph, uint16_t* pl) {
    uint32_t ux = __float_as_uint(v.x), uy = __float_as_uint(v.y);
    uint32_t uz = __float_as_uint(v.z), uw = __float_as_uint(v.w);
    uint32_t h0 = __byte_perm(ux, uy, 0x7632);
    uint32_t h1 = __byte_perm(uz, uw, 0x7632);
    float lx = v.x - __uint_as_float(ux & 0xffff0000u);
    float ly = v.y - __uint_as_float(uy & 0xffff0000u);
    float lz = v.z - __uint_as_float(uz & 0xffff0000u);
    float lw = v.w - __uint_as_float(uw & 0xffff0000u);
    uint32_t l0, l1;
    asm("cvt.rn.bf16x2.f32 %0, %1, %2;" : "=r"(l0) : "f"(ly), "f"(lx));
    asm("cvt.rn.bf16x2.f32 %0, %1, %2;" : "=r"(l1) : "f"(lw), "f"(lz));
    uint2 hv; hv.x = h0; hv.y = h1;
    uint2 lv; lv.x = l0; lv.y = l1;
    *reinterpret_cast<uint2*>(ph) = hv;
    *reinterpret_cast<uint2*>(pl) = lv;
}

__global__ __launch_bounds__(256)
void gemm_freq(const float* __restrict__ X0, const float* __restrict__ X1,
               const float* __restrict__ X2,
               const float* __restrict__ W0, const float* __restrict__ W1,
               const float* __restrict__ W2,
               float* __restrict__ C0, float* __restrict__ C1,
               float* __restrict__ C2,
               int lda, int ldc, int mode)
{
    extern __shared__ uint16_t sm16[];

    const int zt   = blockIdx.z;
    const int z    = zt & 7;
    const int t3   = zt >> 3;
    const float* Xh = (t3 == 0) ? X0 : (t3 == 1) ? X1 : X2;
    const float* Ws = (t3 == 0) ? W0 : (t3 == 1) ? W1 : W2;
    float*       Ch = (t3 == 0) ? C0 : (t3 == 1) ? C1 : C2;

    const int K    = c_kk[mode][z];
    const int aoff = c_aoff[mode][z];
    const int coff = c_coff[mode][z];

    const int tid  = threadIdx.x;
    const int wid  = tid >> 5, lane = tid & 31;
    const int wm   = wid >> 2, wn = wid & 3;
    const int q    = lane >> 2;
    const int t4   = (lane & 3) * 2;

    const size_t m0 = (size_t)blockIdx.y * TM;
    const float* Ab = Xh + m0 * (size_t)lda + aoff;
    const float* Bb = Ws + (size_t)c_woff[z] + (size_t)blockIdx.x * 128 * (size_t)K;

    float acc[4][4][4];
#pragma unroll
    for (int i = 0; i < 4; i++)
#pragma unroll
        for (int j = 0; j < 4; j++)
#pragma unroll
            for (int r = 0; r < 4; r++) acc[i][j][r] = 0.f;

    float4 ra[4], rb[4];
#pragma unroll
    for (int i = 0; i < 4; i++) {
        int e = tid + i * 256, row = e >> 3, k4 = (e & 7) * 4;
        ra[i] = *reinterpret_cast<const float4*>(Ab + (size_t)row * lda + k4);
        rb[i] = *reinterpret_cast<const float4*>(Bb + (size_t)row * K + k4);
    }

    const int NC = K / TK;
    for (int c = 0; c < NC; c++) {
        const int s = c & 1;
        uint16_t* Ah = sm16 + s * STAGE_H;
        uint16_t* Al = Ah + TILE_H;
        uint16_t* Bh = Ah + 2 * TILE_H;
        uint16_t* Bl = Ah + 3 * TILE_H;

#pragma unroll
        for (int i = 0; i < 4; i++) {
            int e = tid + i * 256, row = e >> 3, k4 = (e & 7) * 4;
            int off = row * PADK + k4;
            split_sts(ra[i], Ah + off, Al + off);
            split_sts(rb[i], Bh + off, Bl + off);
        }
        __syncthreads();

        if (c + 1 < NC) {
            int k0 = (c + 1) * TK;
#pragma unroll
            for (int i = 0; i < 4; i++) {
                int e = tid + i * 256, row = e >> 3, k4 = (e & 7) * 4;
                ra[i] = *reinterpret_cast<const float4*>(Ab + (size_t)row * lda + k0 + k4);
                rb[i] = *reinterpret_cast<const float4*>(Bb + (size_t)row * K + k0 + k4);
            }
        }

#pragma unroll
        for (int ks = 0; ks < 2; ks++) {
            const int kb = ks * 16;
            uint32_t ah[4][4], al[4][4], bh[4][2], bl[4][2];
#pragma unroll
            for (int i = 0; i < 4; i++) {
                int r = wm * 64 + i * 16 + q;
                int o00 = r * PADK + kb + t4;
                int o10 = (r + 8) * PADK + kb + t4;
                ah[i][0] = *reinterpret_cast<const uint32_t*>(Ah + o00);
                ah[i][1] = *reinterpret_cast<const uint32_t*>(Ah + o10);
                ah[i][2] = *reinterpret_cast<const uint32_t*>(Ah + o00 + 8);
                ah[i][3] = *reinterpret_cast<const uint32_t*>(Ah + o10 + 8);
                al[i][0] = *reinterpret_cast<const uint32_t*>(Al + o00);
                al[i][1] = *reinterpret_cast<const uint32_t*>(Al + o10);
                al[i][2] = *reinterpret_cast<const uint32_t*>(Al + o00 + 8);
                al[i][3] = *reinterpret_cast<const uint32_t*>(Al + o10 + 8);
            }
#pragma unroll
            for (int j = 0; j < 4; j++) {
                int r = wn * 32 + j * 8 + q;
                int o0 = r * PADK + kb + t4;
                bh[j][0] = *reinterpret_cast<const uint32_t*>(Bh + o0);
                bh[j][1] = *reinterpret_cast<const uint32_t*>(Bh + o0 + 8);
                bl[j][0] = *reinterpret_cast<const uint32_t*>(Bl + o0);
                bl[j][1] = *reinterpret_cast<const uint32_t*>(Bl + o0 + 8);
            }
#pragma unroll
            for (int i = 0; i < 4; i++)
#pragma unroll
                for (int j = 0; j < 4; j++) mma16816(acc[i][j], ah[i], bh[j]);
#pragma unroll
            for (int i = 0; i < 4; i++)
#pragma unroll
                for (int j = 0; j < 4; j++) mma16816(acc[i][j], al[i], bh[j]);
#pragma unroll
            for (int i = 0; i < 4; i++)
#pragma unroll
                for (int j = 0; j < 4; j++) mma16816(acc[i][j], ah[i], bl[j]);
        }
        __syncthreads();
    }

    const int nbase = coff + blockIdx.x * 128;
#pragma unroll
    for (int i = 0; i < 4; i++) {
        size_t r = m0 + wm * 64 + i * 16 + q;
#pragma unroll
        for (int j = 0; j < 4; j++) {
            int cl = nbase + wn * 32 + j * 8 + t4;
            float2 v0, v1;
            v0.x = acc[i][j][0]; v0.y = acc[i][j][1];
            v1.x = acc[i][j][2]; v1.y = acc[i][j][3];
            *reinterpret_cast<float2*>(Ch + r * ldc + cl)       = v0;
            *reinterpret_cast<float2*>(Ch + (r + 8) * ldc + cl) = v1;
        }
    }
}

// ---------------------------------------------------------------------------
// Attention: iFFT staging + proven core; z stored into dead sK column slice
// (warp-private), FFT epilogue warp-local.  smem = 24*ROWSTR*4 = 49.5 KB
// -> 4 CTAs/SM (was 3 with the separate zb buffer).
// ---------------------------------------------------------------------------
#define ROWSTR 516
#define ATTN_SMEM (24 * ROWSTR * 4)

__global__ __launch_bounds__(256)
void attn_freq_kernel(const float* __restrict__ Yq, const float* __restrict__ Yk,
                      const float* __restrict__ Yv,
                      const float* __restrict__ bq, const float* __restrict__ bk,
                      const float* __restrict__ bv,
                      float* __restrict__ Zhat, float* __restrict__ attn_out)
{
    extern __shared__ float sm[];
    float* sQ = sm;
    float* sK = sm + 8 * ROWSTR;
    float* sV = sm + 16 * ROWSTR;

    int b   = blockIdx.x;
    int tid = threadIdx.x;

    const float* srcs[3] = {Yq + (size_t)b * 4096, Yk + (size_t)b * 4096,
                            Yv + (size_t)b * 4096};
    const float* bss[3]  = {bq, bk, bv};
    float* dsts[3] = {sQ, sK, sV};
#pragma unroll
    for (int t3 = 0; t3 < 3; t3++) {
        const float* S = srcs[t3];
        const float* Bp = bss[t3];
        float* D = dsts[t3];
        for (int o = tid; o < 512; o += 256) {
            float f[8], y[8];
#pragma unroll
            for (int p = 0; p < 8; p++) f[p] = S[p * 512 + o];
            ifft8(f, y);
            float bias = Bp[o];
            float* dp = D + (o >> 6) * ROWSTR + (o & 63) * 8;
#pragma unroll
            for (int g = 0; g < 8; g++) dp[g] = y[g] + bias;
        }
    }
    __syncthreads();

    int w    = tid >> 5;
    int lane = tid & 31;
    int base = w * 64;
    int g1a  = lane >> 3;
    int g2   = lane & 7;
    int g1b  = g1a + 4;

    const float* qa = sQ + g1a * ROWSTR + base;
    const float* qb = sQ + g1b * ROWSTR + base;
    const float* kr = sK + g2  * ROWSTR + base;
    float s0 = 0.f, s1 = 0.f;
#pragma unroll 8
    for (int d = 0; d < 64; d++) {
        float kv = kr[d];
        s0 = fmaf(qa[d], kv, s0);
        s1 = fmaf(qb[d], kv, s1);
    }
    s0 *= 0.125f; s1 *= 0.125f;

    float m0 = s0, m1 = s1;
#pragma unroll
    for (int off = 4; off; off >>= 1) {
        m0 = fmaxf(m0, __shfl_xor_sync(0xffffffffu, m0, off));
        m1 = fmaxf(m1, __shfl_xor_sync(0xffffffffu, m1, off));
    }
    float e0 = __expf(s0 - m0), e1 = __expf(s1 - m1);
    float z0 = e0, z1 = e1;
#pragma unroll
    for (int off = 4; off; off >>= 1) {
        z0 += __shfl_xor_sync(0xffffffffu, z0, off);
        z1 += __shfl_xor_sync(0xffffffffu, z1, off);
    }
    float a0 = e0 / z0, a1 = e1 / z1;

    attn_out[(size_t)b * 512 + base + lane]      = a0;
    attn_out[(size_t)b * 512 + base + 32 + lane] = a1;

    __syncwarp();
    sQ[g1a * ROWSTR + base + g2] = a0;
    sQ[g1b * ROWSTR + base + g2] = a1;
    __syncwarp();

    // ---- A*V -> z, stored into the (now dead) sK column slice of this warp:
    //      z[g1][d_local] -> sK[g1*ROWSTR + base + d_local]
#pragma unroll
    for (int g1 = 0; g1 < 8; g1++) {
        const float* ar = sQ + g1 * ROWSTR + base;
        float acc0 = 0.f, acc1 = 0.f;
#pragma unroll
        for (int j = 0; j < 8; j++) {
            float a = ar[j];
            acc0 = fmaf(a, sV[j * ROWSTR + base + lane],      acc0);
            acc1 = fmaf(a, sV[j * ROWSTR + base + 32 + lane], acc1);
        }
        sK[g1 * ROWSTR + base + lane]      = acc0;
        sK[g1 * ROWSTR + base + 32 + lane] = acc1;
    }
    __syncwarp();

    // ---- forward FFT8 over circulant (low-3-bit) octets, warp-local.
    //      octet (g, m) of this warp lives at sK[g*ROWSTR + base + 8m .. +7],
    //      plane spatial index o = g*64 + w*8 + m.
    size_t zr = (size_t)b * 4096;
#pragma unroll
    for (int it = 0; it < 2; it++) {
        int idx = it * 32 + lane;           // 0..63
        int gg = idx >> 3, m = idx & 7;
        const float* zp = sK + gg * ROWSTR + base + m * 8;
        float xx[8], f[8];
#pragma unroll
        for (int j = 0; j < 8; j++) xx[j] = zp[j];
        fft8(xx, f);
        int o = gg * 64 + w * 8 + m;
        Zhat[zr + o]         = f[0];
        Zhat[zr + 512 + o]   = f[7];
        Zhat[zr + 1024 + o]  = f[1];
        Zhat[zr + 1536 + o]  = f[2];
        Zhat[zr + 2048 + o]  = f[3];
        Zhat[zr + 2560 + o]  = f[4];
        Zhat[zr + 3072 + o]  = f[5];
        Zhat[zr + 3584 + o]  = f[6];
    }
}

// ---------------------------------------------------------------------------
// Final: iFFT of FC planes + bias + residual -> out
// ---------------------------------------------------------------------------
__global__ __launch_bounds__(256)
void fc_ifft_kernel(const float* __restrict__ Yf, const float* __restrict__ bias,
                    const float* __restrict__ resid, float* __restrict__ out) {
    int e = blockIdx.x * blockDim.x + threadIdx.x;
    int b = e >> 7, o = e & 127;
    const float* S = Yf + (size_t)b * 1024;
    float f[8], y[8];
#pragma unroll
    for (int p = 0; p < 8; p++) f[p] = S[p * 128 + o];
    ifft8(f, y);
    float bb = bias[o];
    size_t nb = (size_t)b * 1024 + o * 8;
    const float* rp = resid + nb;
    float* op = out + nb;
#pragma unroll
    for (int g = 0; g < 8; g++) op[g] = y[g] + bb + rp[g];
}

// ---------------------------------------------------------------------------
// Launch
// ---------------------------------------------------------------------------
extern "C" void kernel_launch(void* const* d_in, const int* in_sizes, int n_in,
                              void* d_out, int out_size) {
    const float* q    = (const float*)d_in[0];
    const float* k    = (const float*)d_in[1];
    const float* v    = (const float*)d_in[2];
    const float* w_q  = (const float*)d_in[3];
    const float* b_q  = (const float*)d_in[4];
    const float* w_k  = (const float*)d_in[5];
    const float* b_k  = (const float*)d_in[6];
    const float* w_v  = (const float*)d_in[7];
    const float* b_v  = (const float*)d_in[8];
    const float* w_fc = (const float*)d_in[9];
    const float* b_fc = (const float*)d_in[10];

    float* out = (float*)d_out;
    const size_t OUT_ELEMS  = (size_t)BATCH * CDIM;
    const size_t ATTN_ELEMS = (size_t)BATCH * 512;

    float *Xq, *Xk, *Xv, *Wq, *Wk, *Wv, *Wf, *Yq, *Yk, *Yv, *Zh, *Yf, *attnDummy;
    cudaGetSymbolAddress((void**)&Xq, g_Xq);
    cudaGetSymbolAddress((void**)&Xk, g_Xk);
    cudaGetSymbolAddress((void**)&Xv, g_Xv);
    cudaGetSymbolAddress((void**)&Wq, g_Wq);
    cudaGetSymbolAddress((void**)&Wk, g_Wk);
    cudaGetSymbolAddress((void**)&Wv, g_Wv);
    cudaGetSymbolAddress((void**)&Wf, g_Wf);
    cudaGetSymbolAddress((void**)&Yq, g_Yq);
    cudaGetSymbolAddress((void**)&Yk, g_Yk);
    cudaGetSymbolAddress((void**)&Yv, g_Yv);
    cudaGetSymbolAddress((void**)&Zh, g_Zh);
    cudaGetSymbolAddress((void**)&Yf, g_Yf);
    cudaGetSymbolAddress((void**)&attnDummy, g_attn_dummy);

    float* attn_out = ((size_t)out_size >= OUT_ELEMS + ATTN_ELEMS)
                          ? (out + OUT_ELEMS) : attnDummy;

    // 1) forward FFT of activations (fused) and weights (fused)
    dim3 ga(BATCH / 2, 3);
    act_fft3_kernel<<<ga, 256>>>(q, k, v, Xq, Xk, Xv);
    dim3 gw(256, 4);
    wfft4_kernel<<<gw, 256>>>(w_q, w_k, w_v, w_fc, Wq, Wk, Wv, Wf);

    // 2) all 3 projection GEMMs in ONE launch (grid.z = 3 tensors x 8 jobs)
    cudaFuncSetAttribute(gemm_freq, cudaFuncAttributeMaxDynamicSharedMemorySize,
                         GEMM_SMEM_BYTES);
    dim3 gp(4, BATCH / TM, 24);
    gemm_freq<<<gp, 256, GEMM_SMEM_BYTES>>>(Xq, Xk, Xv, Wq, Wk, Wv,
                                            Yq, Yk, Yv, 1024, 4096, 0);

    // 3) attention (iFFT staging + bias; warp-local FFT epilogue -> Zhat)
    cudaFuncSetAttribute(attn_freq_kernel, cudaFuncAttributeMaxDynamicSharedMemorySize,
                         ATTN_SMEM);
    attn_freq_kernel<<<BATCH, 256, ATTN_SMEM>>>(Yq, Yk, Yv, b_q, b_k, b_v,
                                                Zh, attn_out);

    // 4) frequency-domain FC GEMM (single tensor; grid.z = 8 jobs)
    dim3 gf(1, BATCH / TM, 8);
    gemm_freq<<<gf, 256, GEMM_SMEM_BYTES>>>(Zh, Zh, Zh, Wf, Wf, Wf,
                                            Yf, Yf, Yf, 4096, 1024, 1);

    // 5) inverse FFT + bias + residual
    fc_ifft_kernel<<<BATCH * 128 / 256, 256>>>(Yf, b_fc, q, out);
}

// round 15
// speedup vs baseline: 1.2706x; 1.0202x over previous
#include <cuda_runtime.h>
#include <cstdint>

// ---------------------------------------------------------------------------
// Problem constants
// ---------------------------------------------------------------------------
#define BATCH   8192
#define CDIM    1024

// ---------------------------------------------------------------------------
// Device scratch (layouts identical to round-13 passing kernel)
// ---------------------------------------------------------------------------
__device__ float g_Xq[(size_t)BATCH * 1024u];
__device__ float g_Xk[(size_t)BATCH * 1024u];
__device__ float g_Xv[(size_t)BATCH * 1024u];
__device__ float g_Wq[917504u];          // 14 * 512*128
__device__ float g_Wk[917504u];
__device__ float g_Wv[917504u];
__device__ float g_Wf[917504u];          // 14 * 128*512
__device__ float g_Yq[(size_t)BATCH * 4096u];
__device__ float g_Yk[(size_t)BATCH * 4096u];
__device__ float g_Yv[(size_t)BATCH * 4096u];
__device__ float g_Zh[(size_t)BATCH * 4096u];
__device__ float g_Yf[(size_t)BATCH * 1024u];
__device__ float g_attn_dummy[(size_t)BATCH * 512u];

// ---------------------------------------------------------------------------
// GEMM job tables (mode 0 = projection, 1 = fc)
// ---------------------------------------------------------------------------
__constant__ int c_aoff[2][8] = {{0, 256, 256, 512, 512, 768, 768, 128},
                                 {0, 1024, 1024, 2048, 2048, 3072, 3072, 512}};
__constant__ int c_kk[2][8]   = {{128, 256, 256, 256, 256, 256, 256, 128},
                                 {512, 1024, 1024, 1024, 1024, 1024, 1024, 512}};
__constant__ int c_woff[8]    = {0, 65536, 196608, 327680, 458752, 589824, 720896, 851968};
__constant__ int c_coff[2][8] = {{0, 512, 1024, 1536, 2048, 2560, 3072, 3584},
                                 {0, 128, 256, 384, 512, 640, 768, 896}};

// ---------------------------------------------------------------------------
// FFT8 helpers
// ---------------------------------------------------------------------------
#define C1F 0.70710678118654752f

__device__ __forceinline__ void fft8(const float* x, float* f) {
    float t0 = x[0] + x[4], t4 = x[0] - x[4];
    float t1 = x[1] + x[5], t5 = x[1] - x[5];
    float t2 = x[2] + x[6], t6 = x[2] - x[6];
    float t3 = x[3] + x[7], t7 = x[3] - x[7];
    f[0] = t0 + t1 + t2 + t3;
    f[7] = t0 - t1 + t2 - t3;
    f[3] = t0 - t2;
    f[4] = t3 - t1;
    float a = C1F * (t5 - t7), b = C1F * (t5 + t7);
    f[1] = t4 + a;
    f[2] = -t6 - b;
    f[5] = t4 - a;
    f[6] = t6 - b;
}

__device__ __forceinline__ void ifft8(const float* f, float* y) {
    float u0 = 0.5f * (f[0] + f[7]);
    float u1 = 0.5f * (f[0] - f[7]);
    float t0 = 0.5f * (u0 + f[3]);
    float t2 = 0.5f * (u0 - f[3]);
    float t3 = 0.5f * (u1 + f[4]);
    float t1 = 0.5f * (u1 - f[4]);
    float t4 = 0.5f * (f[1] + f[5]);
    float d57 = (f[1] - f[5]) * (0.5f / C1F);
    float t6 = 0.5f * (f[6] - f[2]);
    float s57 = -(f[2] + f[6]) * (0.5f / C1F);
    float t5 = 0.5f * (s57 + d57);
    float t7 = 0.5f * (s57 - d57);
    y[0] = 0.5f * (t0 + t4);  y[4] = 0.5f * (t0 - t4);
    y[1] = 0.5f * (t1 + t5);  y[5] = 0.5f * (t1 - t5);
    y[2] = 0.5f * (t2 + t6);  y[6] = 0.5f * (t2 - t6);
    y[3] = 0.5f * (t3 + t7);  y[7] = 0.5f * (t3 - t7);
}

// ---------------------------------------------------------------------------
// Fused activation forward FFT for q,k,v (grid.y selects tensor)
// ---------------------------------------------------------------------------
__global__ __launch_bounds__(256)
void act_fft3_kernel(const float* __restrict__ x0, const float* __restrict__ x1,
                     const float* __restrict__ x2,
                     float* __restrict__ h0, float* __restrict__ h1,
                     float* __restrict__ h2) {
    __shared__ float s[2 * 1152];
    int blk = blockIdx.x, tid = threadIdx.x;
    const float* x = (blockIdx.y == 0) ? x0 : (blockIdx.y == 1) ? x1 : x2;
    float* xh      = (blockIdx.y == 0) ? h0 : (blockIdx.y == 1) ? h1 : h2;
    size_t base = (size_t)blk * 2048;
#pragma unroll
    for (int i = 0; i < 2; i++) {
        int e = tid + i * 256;
        int row = e >> 8, c4 = e & 255;
        float4 v = reinterpret_cast<const float4*>(x + base + row * 1024)[c4];
        int k = c4 * 4;
        float* d = s + row * 1152 + k + (k >> 3);
        d[0] = v.x; d[1] = v.y; d[2] = v.z; d[3] = v.w;
    }
    __syncthreads();
    int row = tid >> 7, o = tid & 127;
    float xx[8], f[8];
    const float* sp = s + row * 1152 + o * 9;
#pragma unroll
    for (int j = 0; j < 8; j++) xx[j] = sp[j];
    fft8(xx, f);
    size_t ob = (size_t)(blk * 2 + row) * 1024;
    xh[ob + o]       = f[0];
    xh[ob + 128 + o] = f[7];
    xh[ob + 256 + o] = f[1];
    xh[ob + 384 + o] = f[2];
    xh[ob + 512 + o] = f[3];
    xh[ob + 640 + o] = f[4];
    xh[ob + 768 + o] = f[5];
    xh[ob + 896 + o] = f[6];
}

// ---------------------------------------------------------------------------
// Fused weight FFT + job stacking for all 4 weights (grid.y selects weight)
// ---------------------------------------------------------------------------
__global__ void wfft4_kernel(const float* __restrict__ w0, const float* __restrict__ w1,
                             const float* __restrict__ w2, const float* __restrict__ w3,
                             float* __restrict__ s0, float* __restrict__ s1,
                             float* __restrict__ s2, float* __restrict__ s3) {
    int which = blockIdx.y;
    const float* w = (which == 0) ? w0 : (which == 1) ? w1 : (which == 2) ? w2 : w3;
    float* ws      = (which == 0) ? s0 : (which == 1) ? s1 : (which == 2) ? s2 : s3;
    int I = (which == 3) ? 512 : 128;
    int e = blockIdx.x * blockDim.x + threadIdx.x;   // e < 65536 = O*I
    int o = e / I, i = e - o * I;
    float xx[8], f[8];
    const float* wp = w + (size_t)e * 8;
#pragma unroll
    for (int j = 0; j < 8; j++) xx[j] = wp[j];
    fft8(xx, f);
    const size_t OI = 65536u;
    ws[e] = f[0];
    ws[13 * OI + e] = f[7];
#pragma unroll
    for (int m = 1; m <= 3; m++) {
        float re = f[2 * m - 1], im = f[2 * m];
        size_t j1 = OI * (size_t)(4 * m - 3);
        size_t j2 = OI * (size_t)(4 * m - 1);
        size_t rb = (size_t)o * 2 * I + i;
        ws[j1 + rb]     = re;
        ws[j1 + rb + I] = -im;
        ws[j2 + rb]     = im;
        ws[j2 + rb + I] = re;
    }
}

// ---------------------------------------------------------------------------
// GEMM (R10-proven body, UNCHANGED)
// ---------------------------------------------------------------------------
#define TM 128
#define TN 128
#define TK 32
#define PADK 40
#define TILE_H (128 * PADK)
#define STAGE_H (4 * TILE_H)
#define GEMM_SMEM_BYTES (2 * STAGE_H * 2)   // 81,920 B

__device__ __forceinline__ void mma16816(float* c, const uint32_t* a, const uint32_t* b) {
    asm volatile(
        "mma.sync.aligned.m16n8k16.row.col.f32.bf16.bf16.f32 "
        "{%0,%1,%2,%3}, {%4,%5,%6,%7}, {%8,%9}, {%0,%1,%2,%3};"
        : "+f"(c[0]), "+f"(c[1]), "+f"(c[2]), "+f"(c[3])
        : "r"(a[0]), "r"(a[1]), "r"(a[2]), "r"(a[3]), "r"(b[0]), "r"(b[1]));
}

__device__ __forceinline__ void split_sts(float4 v, uint16_t* ph, uint16_t* pl) {
    uint32_t ux = __float_as_uint(v.x), uy = __float_as_uint(v.y);
    uint32_t uz = __float_as_uint(v.z), uw = __float_as_uint(v.w);
    uint32_t h0 = __byte_perm(ux, uy, 0x7632);
    uint32_t h1 = __byte_perm(uz, uw, 0x7632);
    float lx = v.x - __uint_as_float(ux & 0xffff0000u);
    float ly = v.y - __uint_as_float(uy & 0xffff0000u);
    float lz = v.z - __uint_as_float(uz & 0xffff0000u);
    float lw = v.w - __uint_as_float(uw & 0xffff0000u);
    uint32_t l0, l1;
    asm("cvt.rn.bf16x2.f32 %0, %1, %2;" : "=r"(l0) : "f"(ly), "f"(lx));
    asm("cvt.rn.bf16x2.f32 %0, %1, %2;" : "=r"(l1) : "f"(lw), "f"(lz));
    uint2 hv; hv.x = h0; hv.y = h1;
    uint2 lv; lv.x = l0; lv.y = l1;
    *reinterpret_cast<uint2*>(ph) = hv;
    *reinterpret_cast<uint2*>(pl) = lv;
}

__global__ __launch_bounds__(256)
void gemm_freq(const float* __restrict__ X0, const float* __restrict__ X1,
               const float* __restrict__ X2,
               const float* __restrict__ W0, const float* __restrict__ W1,
               const float* __restrict__ W2,
               float* __restrict__ C0, float* __restrict__ C1,
               float* __restrict__ C2,
               int lda, int ldc, int mode)
{
    extern __shared__ uint16_t sm16[];

    const int zt   = blockIdx.z;
    const int z    = zt & 7;
    const int t3   = zt >> 3;
    const float* Xh = (t3 == 0) ? X0 : (t3 == 1) ? X1 : X2;
    const float* Ws = (t3 == 0) ? W0 : (t3 == 1) ? W1 : W2;
    float*       Ch = (t3 == 0) ? C0 : (t3 == 1) ? C1 : C2;

    const int K    = c_kk[mode][z];
    const int aoff = c_aoff[mode][z];
    const int coff = c_coff[mode][z];

    const int tid  = threadIdx.x;
    const int wid  = tid >> 5, lane = tid & 31;
    const int wm   = wid >> 2, wn = wid & 3;
    const int q    = lane >> 2;
    const int t4   = (lane & 3) * 2;

    const size_t m0 = (size_t)blockIdx.y * TM;
    const float* Ab = Xh + m0 * (size_t)lda + aoff;
    const float* Bb = Ws + (size_t)c_woff[z] + (size_t)blockIdx.x * 128 * (size_t)K;

    float acc[4][4][4];
#pragma unroll
    for (int i = 0; i < 4; i++)
#pragma unroll
        for (int j = 0; j < 4; j++)
#pragma unroll
            for (int r = 0; r < 4; r++) acc[i][j][r] = 0.f;

    float4 ra[4], rb[4];
#pragma unroll
    for (int i = 0; i < 4; i++) {
        int e = tid + i * 256, row = e >> 3, k4 = (e & 7) * 4;
        ra[i] = *reinterpret_cast<const float4*>(Ab + (size_t)row * lda + k4);
        rb[i] = *reinterpret_cast<const float4*>(Bb + (size_t)row * K + k4);
    }

    const int NC = K / TK;
    for (int c = 0; c < NC; c++) {
        const int s = c & 1;
        uint16_t* Ah = sm16 + s * STAGE_H;
        uint16_t* Al = Ah + TILE_H;
        uint16_t* Bh = Ah + 2 * TILE_H;
        uint16_t* Bl = Ah + 3 * TILE_H;

#pragma unroll
        for (int i = 0; i < 4; i++) {
            int e = tid + i * 256, row = e >> 3, k4 = (e & 7) * 4;
            int off = row * PADK + k4;
            split_sts(ra[i], Ah + off, Al + off);
            split_sts(rb[i], Bh + off, Bl + off);
        }
        __syncthreads();

        if (c + 1 < NC) {
            int k0 = (c + 1) * TK;
#pragma unroll
            for (int i = 0; i < 4; i++) {
                int e = tid + i * 256, row = e >> 3, k4 = (e & 7) * 4;
                ra[i] = *reinterpret_cast<const float4*>(Ab + (size_t)row * lda + k0 + k4);
                rb[i] = *reinterpret_cast<const float4*>(Bb + (size_t)row * K + k0 + k4);
            }
        }

#pragma unroll
        for (int ks = 0; ks < 2; ks++) {
            const int kb = ks * 16;
            uint32_t ah[4][4], al[4][4], bh[4][2], bl[4][2];
#pragma unroll
            for (int i = 0; i < 4; i++) {
                int r = wm * 64 + i * 16 + q;
                int o00 = r * PADK + kb + t4;
                int o10 = (r + 8) * PADK + kb + t4;
                ah[i][0] = *reinterpret_cast<const uint32_t*>(Ah + o00);
                ah[i][1] = *reinterpret_cast<const uint32_t*>(Ah + o10);
                ah[i][2] = *reinterpret_cast<const uint32_t*>(Ah + o00 + 8);
                ah[i][3] = *reinterpret_cast<const uint32_t*>(Ah + o10 + 8);
                al[i][0] = *reinterpret_cast<const uint32_t*>(Al + o00);
                al[i][1] = *reinterpret_cast<const uint32_t*>(Al + o10);
                al[i][2] = *reinterpret_cast<const uint32_t*>(Al + o00 + 8);
                al[i][3] = *reinterpret_cast<const uint32_t*>(Al + o10 + 8);
            }
#pragma unroll
            for (int j = 0; j < 4; j++) {
                int r = wn * 32 + j * 8 + q;
                int o0 = r * PADK + kb + t4;
                bh[j][0] = *reinterpret_cast<const uint32_t*>(Bh + o0);
                bh[j][1] = *reinterpret_cast<const uint32_t*>(Bh + o0 + 8);
                bl[j][0] = *reinterpret_cast<const uint32_t*>(Bl + o0);
                bl[j][1] = *reinterpret_cast<const uint32_t*>(Bl + o0 + 8);
            }
#pragma unroll
            for (int i = 0; i < 4; i++)
#pragma unroll
                for (int j = 0; j < 4; j++) mma16816(acc[i][j], ah[i], bh[j]);
#pragma unroll
            for (int i = 0; i < 4; i++)
#pragma unroll
                for (int j = 0; j < 4; j++) mma16816(acc[i][j], al[i], bh[j]);
#pragma unroll
            for (int i = 0; i < 4; i++)
#pragma unroll
                for (int j = 0; j < 4; j++) mma16816(acc[i][j], ah[i], bl[j]);
        }
        __syncthreads();
    }

    const int nbase = coff + blockIdx.x * 128;
#pragma unroll
    for (int i = 0; i < 4; i++) {
        size_t r = m0 + wm * 64 + i * 16 + q;
#pragma unroll
        for (int j = 0; j < 4; j++) {
            int cl = nbase + wn * 32 + j * 8 + t4;
            float2 v0, v1;
            v0.x = acc[i][j][0]; v0.y = acc[i][j][1];
            v1.x = acc[i][j][2]; v1.y = acc[i][j][3];
            *reinterpret_cast<float2*>(Ch + r * ldc + cl)       = v0;
            *reinterpret_cast<float2*>(Ch + (r + 8) * ldc + cl) = v1;
        }
    }
}

// ---------------------------------------------------------------------------
// Attention: R13 structure with vectorized (float4) smem staging stores and
// FFT-epilogue loads — identical addresses and arithmetic, 1/4 the L1 ops.
// ---------------------------------------------------------------------------
#define ROWSTR 516
#define ATTN_SMEM (24 * ROWSTR * 4)

__global__ __launch_bounds__(256)
void attn_freq_kernel(const float* __restrict__ Yq, const float* __restrict__ Yk,
                      const float* __restrict__ Yv,
                      const float* __restrict__ bq, const float* __restrict__ bk,
                      const float* __restrict__ bv,
                      float* __restrict__ Zhat, float* __restrict__ attn_out)
{
    extern __shared__ float sm[];
    float* sQ = sm;
    float* sK = sm + 8 * ROWSTR;
    float* sV = sm + 16 * ROWSTR;

    int b   = blockIdx.x;
    int tid = threadIdx.x;

    const float* srcs[3] = {Yq + (size_t)b * 4096, Yk + (size_t)b * 4096,
                            Yv + (size_t)b * 4096};
    const float* bss[3]  = {bq, bk, bv};
    float* dsts[3] = {sQ, sK, sV};
#pragma unroll
    for (int t3 = 0; t3 < 3; t3++) {
        const float* S = srcs[t3];
        const float* Bp = bss[t3];
        float* D = dsts[t3];
        for (int o = tid; o < 512; o += 256) {
            float f[8], y[8];
#pragma unroll
            for (int p = 0; p < 8; p++) f[p] = S[p * 512 + o];
            ifft8(f, y);
            float bias = Bp[o];
            float* dp = D + (o >> 6) * ROWSTR + (o & 63) * 8;
            float4 v0, v1;
            v0.x = y[0] + bias; v0.y = y[1] + bias;
            v0.z = y[2] + bias; v0.w = y[3] + bias;
            v1.x = y[4] + bias; v1.y = y[5] + bias;
            v1.z = y[6] + bias; v1.w = y[7] + bias;
            *reinterpret_cast<float4*>(dp)     = v0;
            *reinterpret_cast<float4*>(dp + 4) = v1;
        }
    }
    __syncthreads();

    int w    = tid >> 5;
    int lane = tid & 31;
    int base = w * 64;
    int g1a  = lane >> 3;
    int g2   = lane & 7;
    int g1b  = g1a + 4;

    const float* qa = sQ + g1a * ROWSTR + base;
    const float* qb = sQ + g1b * ROWSTR + base;
    const float* kr = sK + g2  * ROWSTR + base;
    float s0 = 0.f, s1 = 0.f;
#pragma unroll 8
    for (int d = 0; d < 64; d++) {
        float kv = kr[d];
        s0 = fmaf(qa[d], kv, s0);
        s1 = fmaf(qb[d], kv, s1);
    }
    s0 *= 0.125f; s1 *= 0.125f;

    float m0 = s0, m1 = s1;
#pragma unroll
    for (int off = 4; off; off >>= 1) {
        m0 = fmaxf(m0, __shfl_xor_sync(0xffffffffu, m0, off));
        m1 = fmaxf(m1, __shfl_xor_sync(0xffffffffu, m1, off));
    }
    float e0 = __expf(s0 - m0), e1 = __expf(s1 - m1);
    float z0 = e0, z1 = e1;
#pragma unroll
    for (int off = 4; off; off >>= 1) {
        z0 += __shfl_xor_sync(0xffffffffu, z0, off);
        z1 += __shfl_xor_sync(0xffffffffu, z1, off);
    }
    float a0 = e0 / z0, a1 = e1 / z1;

    attn_out[(size_t)b * 512 + base + lane]      = a0;
    attn_out[(size_t)b * 512 + base + 32 + lane] = a1;

    __syncwarp();
    sQ[g1a * ROWSTR + base + g2] = a0;
    sQ[g1b * ROWSTR + base + g2] = a1;
    __syncwarp();

    // ---- A*V -> z, stored into the (now dead) sK column slice of this warp
#pragma unroll
    for (int g1 = 0; g1 < 8; g1++) {
        const float* ar = sQ + g1 * ROWSTR + base;
        float acc0 = 0.f, acc1 = 0.f;
#pragma unroll
        for (int j = 0; j < 8; j++) {
            float a = ar[j];
            acc0 = fmaf(a, sV[j * ROWSTR + base + lane],      acc0);
            acc1 = fmaf(a, sV[j * ROWSTR + base + 32 + lane], acc1);
        }
        sK[g1 * ROWSTR + base + lane]      = acc0;
        sK[g1 * ROWSTR + base + 32 + lane] = acc1;
    }
    __syncwarp();

    // ---- forward FFT8 over circulant octets, warp-local, float4 loads
    size_t zr = (size_t)b * 4096;
#pragma unroll
    for (int it = 0; it < 2; it++) {
        int idx = it * 32 + lane;           // 0..63
        int gg = idx >> 3, m = idx & 7;
        const float* zp = sK + gg * ROWSTR + base + m * 8;
        float4 za = *reinterpret_cast<const float4*>(zp);
        float4 zb4 = *reinterpret_cast<const float4*>(zp + 4);
        float xx[8], f[8];
        xx[0] = za.x;  xx[1] = za.y;  xx[2] = za.z;  xx[3] = za.w;
        xx[4] = zb4.x; xx[5] = zb4.y; xx[6] = zb4.z; xx[7] = zb4.w;
        fft8(xx, f);
        int o = gg * 64 + w * 8 + m;
        Zhat[zr + o]         = f[0];
        Zhat[zr + 512 + o]   = f[7];
        Zhat[zr + 1024 + o]  = f[1];
        Zhat[zr + 1536 + o]  = f[2];
        Zhat[zr + 2048 + o]  = f[3];
        Zhat[zr + 2560 + o]  = f[4];
        Zhat[zr + 3072 + o]  = f[5];
        Zhat[zr + 3584 + o]  = f[6];
    }
}

// ---------------------------------------------------------------------------
// Final: iFFT of FC planes + bias + residual -> out (float4 resid/out)
// ---------------------------------------------------------------------------
__global__ __launch_bounds__(256)
void fc_ifft_kernel(const float* __restrict__ Yf, const float* __restrict__ bias,
                    const float* __restrict__ resid, float* __restrict__ out) {
    int e = blockIdx.x * blockDim.x + threadIdx.x;
    int b = e >> 7, o = e & 127;
    const float* S = Yf + (size_t)b * 1024;
    float f[8], y[8];
#pragma unroll
    for (int p = 0; p < 8; p++) f[p] = S[p * 128 + o];
    ifft8(f, y);
    float bb = bias[o];
    size_t nb = (size_t)b * 1024 + o * 8;
    float4 r0 = *reinterpret_cast<const float4*>(resid + nb);
    float4 r1 = *reinterpret_cast<const float4*>(resid + nb + 4);
    float4 o0, o1;
    o0.x = y[0] + bb + r0.x; o0.y = y[1] + bb + r0.y;
    o0.z = y[2] + bb + r0.z; o0.w = y[3] + bb + r0.w;
    o1.x = y[4] + bb + r1.x; o1.y = y[5] + bb + r1.y;
    o1.z = y[6] + bb + r1.z; o1.w = y[7] + bb + r1.w;
    *reinterpret_cast<float4*>(out + nb)     = o0;
    *reinterpret_cast<float4*>(out + nb + 4) = o1;
}

// ---------------------------------------------------------------------------
// Launch
// ---------------------------------------------------------------------------
extern "C" void kernel_launch(void* const* d_in, const int* in_sizes, int n_in,
                              void* d_out, int out_size) {
    const float* q    = (const float*)d_in[0];
    const float* k    = (const float*)d_in[1];
    const float* v    = (const float*)d_in[2];
    const float* w_q  = (const float*)d_in[3];
    const float* b_q  = (const float*)d_in[4];
    const float* w_k  = (const float*)d_in[5];
    const float* b_k  = (const float*)d_in[6];
    const float* w_v  = (const float*)d_in[7];
    const float* b_v  = (const float*)d_in[8];
    const float* w_fc = (const float*)d_in[9];
    const float* b_fc = (const float*)d_in[10];

    float* out = (float*)d_out;
    const size_t OUT_ELEMS  = (size_t)BATCH * CDIM;
    const size_t ATTN_ELEMS = (size_t)BATCH * 512;

    float *Xq, *Xk, *Xv, *Wq, *Wk, *Wv, *Wf, *Yq, *Yk, *Yv, *Zh, *Yf, *attnDummy;
    cudaGetSymbolAddress((void**)&Xq, g_Xq);
    cudaGetSymbolAddress((void**)&Xk, g_Xk);
    cudaGetSymbolAddress((void**)&Xv, g_Xv);
    cudaGetSymbolAddress((void**)&Wq, g_Wq);
    cudaGetSymbolAddress((void**)&Wk, g_Wk);
    cudaGetSymbolAddress((void**)&Wv, g_Wv);
    cudaGetSymbolAddress((void**)&Wf, g_Wf);
    cudaGetSymbolAddress((void**)&Yq, g_Yq);
    cudaGetSymbolAddress((void**)&Yk, g_Yk);
    cudaGetSymbolAddress((void**)&Yv, g_Yv);
    cudaGetSymbolAddress((void**)&Zh, g_Zh);
    cudaGetSymbolAddress((void**)&Yf, g_Yf);
    cudaGetSymbolAddress((void**)&attnDummy, g_attn_dummy);

    float* attn_out = ((size_t)out_size >= OUT_ELEMS + ATTN_ELEMS)
                          ? (out + OUT_ELEMS) : attnDummy;

    // 1) forward FFT of activations (fused) and weights (fused)
    dim3 ga(BATCH / 2, 3);
    act_fft3_kernel<<<ga, 256>>>(q, k, v, Xq, Xk, Xv);
    dim3 gw(256, 4);
    wfft4_kernel<<<gw, 256>>>(w_q, w_k, w_v, w_fc, Wq, Wk, Wv, Wf);

    // 2) all 3 projection GEMMs in ONE launch (grid.z = 3 tensors x 8 jobs)
    cudaFuncSetAttribute(gemm_freq, cudaFuncAttributeMaxDynamicSharedMemorySize,
                         GEMM_SMEM_BYTES);
    dim3 gp(4, BATCH / TM, 24);
    gemm_freq<<<gp, 256, GEMM_SMEM_BYTES>>>(Xq, Xk, Xv, Wq, Wk, Wv,
                                            Yq, Yk, Yv, 1024, 4096, 0);

    // 3) attention (iFFT staging + bias; warp-local FFT epilogue -> Zhat)
    cudaFuncSetAttribute(attn_freq_kernel, cudaFuncAttributeMaxDynamicSharedMemorySize,
                         ATTN_SMEM);
    attn_freq_kernel<<<BATCH, 256, ATTN_SMEM>>>(Yq, Yk, Yv, b_q, b_k, b_v,
                                                Zh, attn_out);

    // 4) frequency-domain FC GEMM (single tensor; grid.z = 8 jobs)
    dim3 gf(1, BATCH / TM, 8);
    gemm_freq<<<gf, 256, GEMM_SMEM_BYTES>>>(Zh, Zh, Zh, Wf, Wf, Wf,
                                            Yf, Yf, Yf, 4096, 1024, 1);

    // 5) inverse FFT + bias + residual
    fc_ifft_kernel<<<BATCH * 128 / 256, 256>>>(Yf, b_fc, q, out);
}

// round 16
// speedup vs baseline: 1.2766x; 1.0047x over previous
#include <cuda_runtime.h>
#include <cstdint>

// ---------------------------------------------------------------------------
// Problem constants
// ---------------------------------------------------------------------------
#define BATCH   8192
#define CDIM    1024

// ---------------------------------------------------------------------------
// Device scratch (layouts identical to round-15 passing kernel)
// ---------------------------------------------------------------------------
__device__ float g_Xq[(size_t)BATCH * 1024u];
__device__ float g_Xk[(size_t)BATCH * 1024u];
__device__ float g_Xv[(size_t)BATCH * 1024u];
__device__ float g_Wq[917504u];          // 14 * 512*128
__device__ float g_Wk[917504u];
__device__ float g_Wv[917504u];
__device__ float g_Wf[917504u];          // 14 * 128*512
__device__ float g_Yq[(size_t)BATCH * 4096u];
__device__ float g_Yk[(size_t)BATCH * 4096u];
__device__ float g_Yv[(size_t)BATCH * 4096u];
__device__ float g_Zh[(size_t)BATCH * 4096u];
__device__ float g_Yf[(size_t)BATCH * 1024u];
__device__ float g_attn_dummy[(size_t)BATCH * 512u];

// ---------------------------------------------------------------------------
// GEMM job tables (mode 0 = projection, 1 = fc)
// ---------------------------------------------------------------------------
__constant__ int c_aoff[2][8] = {{0, 256, 256, 512, 512, 768, 768, 128},
                                 {0, 1024, 1024, 2048, 2048, 3072, 3072, 512}};
__constant__ int c_kk[2][8]   = {{128, 256, 256, 256, 256, 256, 256, 128},
                                 {512, 1024, 1024, 1024, 1024, 1024, 1024, 512}};
__constant__ int c_woff[8]    = {0, 65536, 196608, 327680, 458752, 589824, 720896, 851968};
__constant__ int c_coff[2][8] = {{0, 512, 1024, 1536, 2048, 2560, 3072, 3584},
                                 {0, 128, 256, 384, 512, 640, 768, 896}};

// ---------------------------------------------------------------------------
// FFT8 helpers
// ---------------------------------------------------------------------------
#define C1F 0.70710678118654752f

__device__ __forceinline__ void fft8(const float* x, float* f) {
    float t0 = x[0] + x[4], t4 = x[0] - x[4];
    float t1 = x[1] + x[5], t5 = x[1] - x[5];
    float t2 = x[2] + x[6], t6 = x[2] - x[6];
    float t3 = x[3] + x[7], t7 = x[3] - x[7];
    f[0] = t0 + t1 + t2 + t3;
    f[7] = t0 - t1 + t2 - t3;
    f[3] = t0 - t2;
    f[4] = t3 - t1;
    float a = C1F * (t5 - t7), b = C1F * (t5 + t7);
    f[1] = t4 + a;
    f[2] = -t6 - b;
    f[5] = t4 - a;
    f[6] = t6 - b;
}

__device__ __forceinline__ void ifft8(const float* f, float* y) {
    float u0 = 0.5f * (f[0] + f[7]);
    float u1 = 0.5f * (f[0] - f[7]);
    float t0 = 0.5f * (u0 + f[3]);
    float t2 = 0.5f * (u0 - f[3]);
    float t3 = 0.5f * (u1 + f[4]);
    float t1 = 0.5f * (u1 - f[4]);
    float t4 = 0.5f * (f[1] + f[5]);
    float d57 = (f[1] - f[5]) * (0.5f / C1F);
    float t6 = 0.5f * (f[6] - f[2]);
    float s57 = -(f[2] + f[6]) * (0.5f / C1F);
    float t5 = 0.5f * (s57 + d57);
    float t7 = 0.5f * (s57 - d57);
    y[0] = 0.5f * (t0 + t4);  y[4] = 0.5f * (t0 - t4);
    y[1] = 0.5f * (t1 + t5);  y[5] = 0.5f * (t1 - t5);
    y[2] = 0.5f * (t2 + t6);  y[6] = 0.5f * (t2 - t6);
    y[3] = 0.5f * (t3 + t7);  y[7] = 0.5f * (t3 - t7);
}

// ---------------------------------------------------------------------------
// Fused activation forward FFT for q,k,v (grid.y selects tensor)
// ---------------------------------------------------------------------------
__global__ __launch_bounds__(256)
void act_fft3_kernel(const float* __restrict__ x0, const float* __restrict__ x1,
                     const float* __restrict__ x2,
                     float* __restrict__ h0, float* __restrict__ h1,
                     float* __restrict__ h2) {
    __shared__ float s[2 * 1152];
    int blk = blockIdx.x, tid = threadIdx.x;
    const float* x = (blockIdx.y == 0) ? x0 : (blockIdx.y == 1) ? x1 : x2;
    float* xh      = (blockIdx.y == 0) ? h0 : (blockIdx.y == 1) ? h1 : h2;
    size_t base = (size_t)blk * 2048;
#pragma unroll
    for (int i = 0; i < 2; i++) {
        int e = tid + i * 256;
        int row = e >> 8, c4 = e & 255;
        float4 v = reinterpret_cast<const float4*>(x + base + row * 1024)[c4];
        int k = c4 * 4;
        float* d = s + row * 1152 + k + (k >> 3);
        d[0] = v.x; d[1] = v.y; d[2] = v.z; d[3] = v.w;
    }
    __syncthreads();
    int row = tid >> 7, o = tid & 127;
    float xx[8], f[8];
    const float* sp = s + row * 1152 + o * 9;
#pragma unroll
    for (int j = 0; j < 8; j++) xx[j] = sp[j];
    fft8(xx, f);
    size_t ob = (size_t)(blk * 2 + row) * 1024;
    xh[ob + o]       = f[0];
    xh[ob + 128 + o] = f[7];
    xh[ob + 256 + o] = f[1];
    xh[ob + 384 + o] = f[2];
    xh[ob + 512 + o] = f[3];
    xh[ob + 640 + o] = f[4];
    xh[ob + 768 + o] = f[5];
    xh[ob + 896 + o] = f[6];
}

// ---------------------------------------------------------------------------
// Fused weight FFT + job stacking for all 4 weights (grid.y selects weight)
// ---------------------------------------------------------------------------
__global__ void wfft4_kernel(const float* __restrict__ w0, const float* __restrict__ w1,
                             const float* __restrict__ w2, const float* __restrict__ w3,
                             float* __restrict__ s0, float* __restrict__ s1,
                             float* __restrict__ s2, float* __restrict__ s3) {
    int which = blockIdx.y;
    const float* w = (which == 0) ? w0 : (which == 1) ? w1 : (which == 2) ? w2 : w3;
    float* ws      = (which == 0) ? s0 : (which == 1) ? s1 : (which == 2) ? s2 : s3;
    int I = (which == 3) ? 512 : 128;
    int e = blockIdx.x * blockDim.x + threadIdx.x;   // e < 65536 = O*I
    int o = e / I, i = e - o * I;
    float xx[8], f[8];
    const float* wp = w + (size_t)e * 8;
#pragma unroll
    for (int j = 0; j < 8; j++) xx[j] = wp[j];
    fft8(xx, f);
    const size_t OI = 65536u;
    ws[e] = f[0];
    ws[13 * OI + e] = f[7];
#pragma unroll
    for (int m = 1; m <= 3; m++) {
        float re = f[2 * m - 1], im = f[2 * m];
        size_t j1 = OI * (size_t)(4 * m - 3);
        size_t j2 = OI * (size_t)(4 * m - 1);
        size_t rb = (size_t)o * 2 * I + i;
        ws[j1 + rb]     = re;
        ws[j1 + rb + I] = -im;
        ws[j2 + rb]     = im;
        ws[j2 + rb + I] = re;
    }
}

// ---------------------------------------------------------------------------
// GEMM (R10-proven body, UNCHANGED)
// ---------------------------------------------------------------------------
#define TM 128
#define TN 128
#define TK 32
#define PADK 40
#define TILE_H (128 * PADK)
#define STAGE_H (4 * TILE_H)
#define GEMM_SMEM_BYTES (2 * STAGE_H * 2)   // 81,920 B

__device__ __forceinline__ void mma16816(float* c, const uint32_t* a, const uint32_t* b) {
    asm volatile(
        "mma.sync.aligned.m16n8k16.row.col.f32.bf16.bf16.f32 "
        "{%0,%1,%2,%3}, {%4,%5,%6,%7}, {%8,%9}, {%0,%1,%2,%3};"
        : "+f"(c[0]), "+f"(c[1]), "+f"(c[2]), "+f"(c[3])
        : "r"(a[0]), "r"(a[1]), "r"(a[2]), "r"(a[3]), "r"(b[0]), "r"(b[1]));
}

__device__ __forceinline__ void split_sts(float4 v, uint16_t* ph, uint16_t* pl) {
    uint32_t ux = __float_as_uint(v.x), uy = __float_as_uint(v.y);
    uint32_t uz = __float_as_uint(v.z), uw = __float_as_uint(v.w);
    uint32_t h0 = __byte_perm(ux, uy, 0x7632);
    uint32_t h1 = __byte_perm(uz, uw, 0x7632);
    float lx = v.x - __uint_as_float(ux & 0xffff0000u);
    float ly = v.y - __uint_as_float(uy & 0xffff0000u);
    float lz = v.z - __uint_as_float(uz & 0xffff0000u);
    float lw = v.w - __uint_as_float(uw & 0xffff0000u);
    uint32_t l0, l1;
    asm("cvt.rn.bf16x2.f32 %0, %1, %2;" : "=r"(l0) : "f"(ly), "f"(lx));
    asm("cvt.rn.bf16x2.f32 %0, %1, %2;" : "=r"(l1) : "f"(lw), "f"(lz));
    uint2 hv; hv.x = h0; hv.y = h1;
    uint2 lv; lv.x = l0; lv.y = l1;
    *reinterpret_cast<uint2*>(ph) = hv;
    *reinterpret_cast<uint2*>(pl) = lv;
}

__global__ __launch_bounds__(256)
void gemm_freq(const float* __restrict__ X0, const float* __restrict__ X1,
               const float* __restrict__ X2,
               const float* __restrict__ W0, const float* __restrict__ W1,
               const float* __restrict__ W2,
               float* __restrict__ C0, float* __restrict__ C1,
               float* __restrict__ C2,
               int lda, int ldc, int mode)
{
    extern __shared__ uint16_t sm16[];

    const int zt   = blockIdx.z;
    const int z    = zt & 7;
    const int t3   = zt >> 3;
    const float* Xh = (t3 == 0) ? X0 : (t3 == 1) ? X1 : X2;
    const float* Ws = (t3 == 0) ? W0 : (t3 == 1) ? W1 : W2;
    float*       Ch = (t3 == 0) ? C0 : (t3 == 1) ? C1 : C2;

    const int K    = c_kk[mode][z];
    const int aoff = c_aoff[mode][z];
    const int coff = c_coff[mode][z];

    const int tid  = threadIdx.x;
    const int wid  = tid >> 5, lane = tid & 31;
    const int wm   = wid >> 2, wn = wid & 3;
    const int q    = lane >> 2;
    const int t4   = (lane & 3) * 2;

    const size_t m0 = (size_t)blockIdx.y * TM;
    const float* Ab = Xh + m0 * (size_t)lda + aoff;
    const float* Bb = Ws + (size_t)c_woff[z] + (size_t)blockIdx.x * 128 * (size_t)K;

    float acc[4][4][4];
#pragma unroll
    for (int i = 0; i < 4; i++)
#pragma unroll
        for (int j = 0; j < 4; j++)
#pragma unroll
            for (int r = 0; r < 4; r++) acc[i][j][r] = 0.f;

    float4 ra[4], rb[4];
#pragma unroll
    for (int i = 0; i < 4; i++) {
        int e = tid + i * 256, row = e >> 3, k4 = (e & 7) * 4;
        ra[i] = *reinterpret_cast<const float4*>(Ab + (size_t)row * lda + k4);
        rb[i] = *reinterpret_cast<const float4*>(Bb + (size_t)row * K + k4);
    }

    const int NC = K / TK;
    for (int c = 0; c < NC; c++) {
        const int s = c & 1;
        uint16_t* Ah = sm16 + s * STAGE_H;
        uint16_t* Al = Ah + TILE_H;
        uint16_t* Bh = Ah + 2 * TILE_H;
        uint16_t* Bl = Ah + 3 * TILE_H;

#pragma unroll
        for (int i = 0; i < 4; i++) {
            int e = tid + i * 256, row = e >> 3, k4 = (e & 7) * 4;
            int off = row * PADK + k4;
            split_sts(ra[i], Ah + off, Al + off);
            split_sts(rb[i], Bh + off, Bl + off);
        }
        __syncthreads();

        if (c + 1 < NC) {
            int k0 = (c + 1) * TK;
#pragma unroll
            for (int i = 0; i < 4; i++) {
                int e = tid + i * 256, row = e >> 3, k4 = (e & 7) * 4;
                ra[i] = *reinterpret_cast<const float4*>(Ab + (size_t)row * lda + k0 + k4);
                rb[i] = *reinterpret_cast<const float4*>(Bb + (size_t)row * K + k0 + k4);
            }
        }

#pragma unroll
        for (int ks = 0; ks < 2; ks++) {
            const int kb = ks * 16;
            uint32_t ah[4][4], al[4][4], bh[4][2], bl[4][2];
#pragma unroll
            for (int i = 0; i < 4; i++) {
                int r = wm * 64 + i * 16 + q;
                int o00 = r * PADK + kb + t4;
                int o10 = (r + 8) * PADK + kb + t4;
                ah[i][0] = *reinterpret_cast<const uint32_t*>(Ah + o00);
                ah[i][1] = *reinterpret_cast<const uint32_t*>(Ah + o10);
                ah[i][2] = *reinterpret_cast<const uint32_t*>(Ah + o00 + 8);
                ah[i][3] = *reinterpret_cast<const uint32_t*>(Ah + o10 + 8);
                al[i][0] = *reinterpret_cast<const uint32_t*>(Al + o00);
                al[i][1] = *reinterpret_cast<const uint32_t*>(Al + o10);
                al[i][2] = *reinterpret_cast<const uint32_t*>(Al + o00 + 8);
                al[i][3] = *reinterpret_cast<const uint32_t*>(Al + o10 + 8);
            }
#pragma unroll
            for (int j = 0; j < 4; j++) {
                int r = wn * 32 + j * 8 + q;
                int o0 = r * PADK + kb + t4;
                bh[j][0] = *reinterpret_cast<const uint32_t*>(Bh + o0);
                bh[j][1] = *reinterpret_cast<const uint32_t*>(Bh + o0 + 8);
                bl[j][0] = *reinterpret_cast<const uint32_t*>(Bl + o0);
                bl[j][1] = *reinterpret_cast<const uint32_t*>(Bl + o0 + 8);
            }
#pragma unroll
            for (int i = 0; i < 4; i++)
#pragma unroll
                for (int j = 0; j < 4; j++) mma16816(acc[i][j], ah[i], bh[j]);
#pragma unroll
            for (int i = 0; i < 4; i++)
#pragma unroll
                for (int j = 0; j < 4; j++) mma16816(acc[i][j], al[i], bh[j]);
#pragma unroll
            for (int i = 0; i < 4; i++)
#pragma unroll
                for (int j = 0; j < 4; j++) mma16816(acc[i][j], ah[i], bl[j]);
        }
        __syncthreads();
    }

    const int nbase = coff + blockIdx.x * 128;
#pragma unroll
    for (int i = 0; i < 4; i++) {
        size_t r = m0 + wm * 64 + i * 16 + q;
#pragma unroll
        for (int j = 0; j < 4; j++) {
            int cl = nbase + wn * 32 + j * 8 + t4;
            float2 v0, v1;
            v0.x = acc[i][j][0]; v0.y = acc[i][j][1];
            v1.x = acc[i][j][2]; v1.y = acc[i][j][3];
            *reinterpret_cast<float2*>(Ch + r * ldc + cl)       = v0;
            *reinterpret_cast<float2*>(Ch + (r + 8) * ldc + cl) = v1;
        }
    }
}

// ---------------------------------------------------------------------------
// Attention: R15 structure; compute-loop operand loads vectorized (float4).
// Same arithmetic order -> bit-identical results.
// ---------------------------------------------------------------------------
#define ROWSTR 516
#define ATTN_SMEM (24 * ROWSTR * 4)

__global__ __launch_bounds__(256)
void attn_freq_kernel(const float* __restrict__ Yq, const float* __restrict__ Yk,
                      const float* __restrict__ Yv,
                      const float* __restrict__ bq, const float* __restrict__ bk,
                      const float* __restrict__ bv,
                      float* __restrict__ Zhat, float* __restrict__ attn_out)
{
    extern __shared__ float sm[];
    float* sQ = sm;
    float* sK = sm + 8 * ROWSTR;
    float* sV = sm + 16 * ROWSTR;

    int b   = blockIdx.x;
    int tid = threadIdx.x;

    const float* srcs[3] = {Yq + (size_t)b * 4096, Yk + (size_t)b * 4096,
                            Yv + (size_t)b * 4096};
    const float* bss[3]  = {bq, bk, bv};
    float* dsts[3] = {sQ, sK, sV};
#pragma unroll
    for (int t3 = 0; t3 < 3; t3++) {
        const float* S = srcs[t3];
        const float* Bp = bss[t3];
        float* D = dsts[t3];
        for (int o = tid; o < 512; o += 256) {
            float f[8], y[8];
#pragma unroll
            for (int p = 0; p < 8; p++) f[p] = S[p * 512 + o];
            ifft8(f, y);
            float bias = Bp[o];
            float* dp = D + (o >> 6) * ROWSTR + (o & 63) * 8;
            float4 v0, v1;
            v0.x = y[0] + bias; v0.y = y[1] + bias;
            v0.z = y[2] + bias; v0.w = y[3] + bias;
            v1.x = y[4] + bias; v1.y = y[5] + bias;
            v1.z = y[6] + bias; v1.w = y[7] + bias;
            *reinterpret_cast<float4*>(dp)     = v0;
            *reinterpret_cast<float4*>(dp + 4) = v1;
        }
    }
    __syncthreads();

    int w    = tid >> 5;
    int lane = tid & 31;
    int base = w * 64;
    int g1a  = lane >> 3;
    int g2   = lane & 7;
    int g1b  = g1a + 4;

    // ---- scores via float4 operand loads (same accumulation order)
    const float4* qa4 = reinterpret_cast<const float4*>(sQ + g1a * ROWSTR + base);
    const float4* qb4 = reinterpret_cast<const float4*>(sQ + g1b * ROWSTR + base);
    const float4* kr4 = reinterpret_cast<const float4*>(sK + g2  * ROWSTR + base);
    float s0 = 0.f, s1 = 0.f;
#pragma unroll
    for (int d4 = 0; d4 < 16; d4++) {
        float4 kv = kr4[d4];
        float4 va = qa4[d4];
        float4 vb = qb4[d4];
        s0 = fmaf(va.x, kv.x, s0); s1 = fmaf(vb.x, kv.x, s1);
        s0 = fmaf(va.y, kv.y, s0); s1 = fmaf(vb.y, kv.y, s1);
        s0 = fmaf(va.z, kv.z, s0); s1 = fmaf(vb.z, kv.z, s1);
        s0 = fmaf(va.w, kv.w, s0); s1 = fmaf(vb.w, kv.w, s1);
    }
    s0 *= 0.125f; s1 *= 0.125f;

    float m0 = s0, m1 = s1;
#pragma unroll
    for (int off = 4; off; off >>= 1) {
        m0 = fmaxf(m0, __shfl_xor_sync(0xffffffffu, m0, off));
        m1 = fmaxf(m1, __shfl_xor_sync(0xffffffffu, m1, off));
    }
    float e0 = __expf(s0 - m0), e1 = __expf(s1 - m1);
    float z0 = e0, z1 = e1;
#pragma unroll
    for (int off = 4; off; off >>= 1) {
        z0 += __shfl_xor_sync(0xffffffffu, z0, off);
        z1 += __shfl_xor_sync(0xffffffffu, z1, off);
    }
    float a0 = e0 / z0, a1 = e1 / z1;

    attn_out[(size_t)b * 512 + base + lane]      = a0;
    attn_out[(size_t)b * 512 + base + 32 + lane] = a1;

    __syncwarp();
    sQ[g1a * ROWSTR + base + g2] = a0;
    sQ[g1b * ROWSTR + base + g2] = a1;
    __syncwarp();

    // ---- A*V -> z into dead sK slice; attn-weight row loaded as 2 float4
#pragma unroll
    for (int g1 = 0; g1 < 8; g1++) {
        const float4* ar4 = reinterpret_cast<const float4*>(sQ + g1 * ROWSTR + base);
        float4 w0 = ar4[0];
        float4 w1 = ar4[1];
        float aw[8] = {w0.x, w0.y, w0.z, w0.w, w1.x, w1.y, w1.z, w1.w};
        float acc0 = 0.f, acc1 = 0.f;
#pragma unroll
        for (int j = 0; j < 8; j++) {
            acc0 = fmaf(aw[j], sV[j * ROWSTR + base + lane],      acc0);
            acc1 = fmaf(aw[j], sV[j * ROWSTR + base + 32 + lane], acc1);
        }
        sK[g1 * ROWSTR + base + lane]      = acc0;
        sK[g1 * ROWSTR + base + 32 + lane] = acc1;
    }
    __syncwarp();

    // ---- forward FFT8 over circulant octets, warp-local, float4 loads
    size_t zr = (size_t)b * 4096;
#pragma unroll
    for (int it = 0; it < 2; it++) {
        int idx = it * 32 + lane;           // 0..63
        int gg = idx >> 3, m = idx & 7;
        const float* zp = sK + gg * ROWSTR + base + m * 8;
        float4 za = *reinterpret_cast<const float4*>(zp);
        float4 zb4 = *reinterpret_cast<const float4*>(zp + 4);
        float xx[8], f[8];
        xx[0] = za.x;  xx[1] = za.y;  xx[2] = za.z;  xx[3] = za.w;
        xx[4] = zb4.x; xx[5] = zb4.y; xx[6] = zb4.z; xx[7] = zb4.w;
        fft8(xx, f);
        int o = gg * 64 + w * 8 + m;
        Zhat[zr + o]         = f[0];
        Zhat[zr + 512 + o]   = f[7];
        Zhat[zr + 1024 + o]  = f[1];
        Zhat[zr + 1536 + o]  = f[2];
        Zhat[zr + 2048 + o]  = f[3];
        Zhat[zr + 2560 + o]  = f[4];
        Zhat[zr + 3072 + o]  = f[5];
        Zhat[zr + 3584 + o]  = f[6];
    }
}

// ---------------------------------------------------------------------------
// Final: iFFT of FC planes + bias + residual -> out (float4 resid/out)
// ---------------------------------------------------------------------------
__global__ __launch_bounds__(256)
void fc_ifft_kernel(const float* __restrict__ Yf, const float* __restrict__ bias,
                    const float* __restrict__ resid, float* __restrict__ out) {
    int e = blockIdx.x * blockDim.x + threadIdx.x;
    int b = e >> 7, o = e & 127;
    const float* S = Yf + (size_t)b * 1024;
    float f[8], y[8];
#pragma unroll
    for (int p = 0; p < 8; p++) f[p] = S[p * 128 + o];
    ifft8(f, y);
    float bb = bias[o];
    size_t nb = (size_t)b * 1024 + o * 8;
    float4 r0 = *reinterpret_cast<const float4*>(resid + nb);
    float4 r1 = *reinterpret_cast<const float4*>(resid + nb + 4);
    float4 o0, o1;
    o0.x = y[0] + bb + r0.x; o0.y = y[1] + bb + r0.y;
    o0.z = y[2] + bb + r0.z; o0.w = y[3] + bb + r0.w;
    o1.x = y[4] + bb + r1.x; o1.y = y[5] + bb + r1.y;
    o1.z = y[6] + bb + r1.z; o1.w = y[7] + bb + r1.w;
    *reinterpret_cast<float4*>(out + nb)     = o0;
    *reinterpret_cast<float4*>(out + nb + 4) = o1;
}

// ---------------------------------------------------------------------------
// Launch
// ---------------------------------------------------------------------------
extern "C" void kernel_launch(void* const* d_in, const int* in_sizes, int n_in,
                              void* d_out, int out_size) {
    const float* q    = (const float*)d_in[0];
    const float* k    = (const float*)d_in[1];
    const float* v    = (const float*)d_in[2];
    const float* w_q  = (const float*)d_in[3];
    const float* b_q  = (const float*)d_in[4];
    const float* w_k  = (const float*)d_in[5];
    const float* b_k  = (const float*)d_in[6];
    const float* w_v  = (const float*)d_in[7];
    const float* b_v  = (const float*)d_in[8];
    const float* w_fc = (const float*)d_in[9];
    const float* b_fc = (const float*)d_in[10];

    float* out = (float*)d_out;
    const size_t OUT_ELEMS  = (size_t)BATCH * CDIM;
    const size_t ATTN_ELEMS = (size_t)BATCH * 512;

    float *Xq, *Xk, *Xv, *Wq, *Wk, *Wv, *Wf, *Yq, *Yk, *Yv, *Zh, *Yf, *attnDummy;
    cudaGetSymbolAddress((void**)&Xq, g_Xq);
    cudaGetSymbolAddress((void**)&Xk, g_Xk);
    cudaGetSymbolAddress((void**)&Xv, g_Xv);
    cudaGetSymbolAddress((void**)&Wq, g_Wq);
    cudaGetSymbolAddress((void**)&Wk, g_Wk);
    cudaGetSymbolAddress((void**)&Wv, g_Wv);
    cudaGetSymbolAddress((void**)&Wf, g_Wf);
    cudaGetSymbolAddress((void**)&Yq, g_Yq);
    cudaGetSymbolAddress((void**)&Yk, g_Yk);
    cudaGetSymbolAddress((void**)&Yv, g_Yv);
    cudaGetSymbolAddress((void**)&Zh, g_Zh);
    cudaGetSymbolAddress((void**)&Yf, g_Yf);
    cudaGetSymbolAddress((void**)&attnDummy, g_attn_dummy);

    float* attn_out = ((size_t)out_size >= OUT_ELEMS + ATTN_ELEMS)
                          ? (out + OUT_ELEMS) : attnDummy;

    // 1) forward FFT of activations (fused) and weights (fused)
    dim3 ga(BATCH / 2, 3);
    act_fft3_kernel<<<ga, 256>>>(q, k, v, Xq, Xk, Xv);
    dim3 gw(256, 4);
    wfft4_kernel<<<gw, 256>>>(w_q, w_k, w_v, w_fc, Wq, Wk, Wv, Wf);

    // 2) all 3 projection GEMMs in ONE launch (grid.z = 3 tensors x 8 jobs)
    cudaFuncSetAttribute(gemm_freq, cudaFuncAttributeMaxDynamicSharedMemorySize,
                         GEMM_SMEM_BYTES);
    dim3 gp(4, BATCH / TM, 24);
    gemm_freq<<<gp, 256, GEMM_SMEM_BYTES>>>(Xq, Xk, Xv, Wq, Wk, Wv,
                                            Yq, Yk, Yv, 1024, 4096, 0);

    // 3) attention (iFFT staging + bias; warp-local FFT epilogue -> Zhat)
    cudaFuncSetAttribute(attn_freq_kernel, cudaFuncAttributeMaxDynamicSharedMemorySize,
                         ATTN_SMEM);
    attn_freq_kernel<<<BATCH, 256, ATTN_SMEM>>>(Yq, Yk, Yv, b_q, b_k, b_v,
                                                Zh, attn_out);

    // 4) frequency-domain FC GEMM (single tensor; grid.z = 8 jobs)
    dim3 gf(1, BATCH / TM, 8);
    gemm_freq<<<gf, 256, GEMM_SMEM_BYTES>>>(Zh, Zh, Zh, Wf, Wf, Wf,
                                            Yf, Yf, Yf, 4096, 1024, 1);

    // 5) inverse FFT + bias + residual
    fc_ifft_kernel<<<BATCH * 128 / 256, 256>>>(Yf, b_fc, q, out);
}